// round 7
// baseline (speedup 1.0000x reference)
#include <cuda_runtime.h>
#include <cuda_fp16.h>
#include <cstdint>

#define M_DIM 4096
#define K_DIM 4096
#define N_DIM 12288

// GEMM tiling
constexpr int BM = 128, BN = 256, BK = 64;
constexpr int KT = K_DIM / BK;                 // 64 k-tiles per output tile
constexpr int NTILES = (M_DIM / BM) * (N_DIM / BN);   // 1536
constexpr int NST = 4;                         // pipeline stages
constexpr int A_TILE = BM * BK * 2;            // 16384 B
constexpr int B_TILE = BN * BK * 2;            // 32768 B
constexpr int STAGE_BYTES = A_TILE + B_TILE;   // 49152
constexpr int SMEM_OFF = 1024;
constexpr int SMEM_BYTES = SMEM_OFF + NST * STAGE_BYTES;   // 197632

// tile-packed, pre-swizzled operand blobs
__device__ __half g_Apack[(size_t)M_DIM * K_DIM];   // tiles (mb*64+kt): 128x64, 128B rows
__device__ __half g_Bpack[(size_t)N_DIM * K_DIM];   // tiles (nb*64+kt): 256x64 [n][k]

// chunk swizzle within 128B row: 16B chunk c (0..7), row r -> c ^ (r & 7)

// ---------------------------------------------------------------------------
// Pack A: fp32 [M,K] -> fp16 swizzled 128x64 tiles
// ---------------------------------------------------------------------------
__global__ void convA_kernel(const float* __restrict__ A) {
    int id = blockIdx.x * 256 + threadIdx.x;    // M*512 16B-chunk ids
    int m = id >> 9;
    int ch = id & 511;
    int kt = ch >> 3, c = ch & 7;
    const float4* src = reinterpret_cast<const float4*>(
        A + (size_t)m * K_DIM + kt * 64 + c * 8);
    float4 v0 = src[0], v1 = src[1];
    __half2 h[4];
    h[0] = __floats2half2_rn(v0.x, v0.y);
    h[1] = __floats2half2_rn(v0.z, v0.w);
    h[2] = __floats2half2_rn(v1.x, v1.y);
    h[3] = __floats2half2_rn(v1.z, v1.w);
    int mb = m >> 7, r = m & 127;
    int cs = c ^ (r & 7);
    char* dst = (char*)g_Apack + (size_t)(mb * 64 + kt) * A_TILE + r * 128 + cs * 16;
    *reinterpret_cast<uint4*>(dst) = *reinterpret_cast<uint4*>(h);
}

// ---------------------------------------------------------------------------
// Dequant+pack W: int4 -> fp16 swizzled 256x64 [n][k] tiles
// thread (t,o): k = t*16 + c8*8 + j, n = o
// ---------------------------------------------------------------------------
__global__ void dequant_kernel(const int* __restrict__ B, const float* __restrict__ s) {
    int id = blockIdx.x * 256 + threadIdx.x;    // (K/16)*N ids
    int t = id / N_DIM, o = id - t * N_DIM;
    int2 p = reinterpret_cast<const int2*>(B)[(size_t)t * N_DIM + o];
    float sc = s[(t >> 3) * N_DIM + o];
    __half2 h[8];
#pragma unroll
    for (int c8 = 0; c8 < 2; c8++) {
        int v = c8 ? p.y : p.x;
#pragma unroll
        for (int j = 0; j < 4; j++) {
            float w0 = (float)(((v >> (8 * j)) & 0xF) - 8) * sc;
            float w1 = (float)(((v >> (8 * j + 4)) & 0xF) - 8) * sc;
            h[c8 * 4 + j] = __floats2half2_rn(w0, w1);
        }
    }
    int kt = t >> 2;                 // 4 t-rows per 64-k tile
    int nb = o >> 8, r = o & 255;
    char* tile = (char*)g_Bpack + (size_t)(nb * 64 + kt) * B_TILE;
    int c0 = (t & 3) * 2;
    int xm = r & 7;
    *reinterpret_cast<uint4*>(tile + r * 128 + (c0 ^ xm) * 16)       = *reinterpret_cast<uint4*>(h);
    *reinterpret_cast<uint4*>(tile + r * 128 + ((c0 + 1) ^ xm) * 16) = *reinterpret_cast<uint4*>(h + 4);
}

// ---------------------------------------------------------------------------
// helpers
// ---------------------------------------------------------------------------
__device__ __forceinline__ uint32_t smem_u32(const void* p) {
    return (uint32_t)__cvta_generic_to_shared(p);
}
__device__ __forceinline__ void mbar_init(uint32_t a, uint32_t cnt) {
    asm volatile("mbarrier.init.shared.b64 [%0], %1;" :: "r"(a), "r"(cnt) : "memory");
}
__device__ __forceinline__ void mbar_expect_tx(uint32_t a, uint32_t bytes) {
    asm volatile("mbarrier.arrive.expect_tx.shared.b64 _, [%0], %1;"
                 :: "r"(a), "r"(bytes) : "memory");
}
__device__ __forceinline__ void mbar_arrive(uint32_t a) {
    asm volatile("mbarrier.arrive.shared.b64 _, [%0];" :: "r"(a) : "memory");
}
__device__ __forceinline__ void mbar_wait(uint32_t a, uint32_t parity) {
    asm volatile(
        "{\n\t.reg .pred P;\n"
        "W0_%=:\n\t"
        "mbarrier.try_wait.parity.acquire.cta.shared::cta.b64 P, [%0], %1, 0x989680;\n\t"
        "@P bra.uni W1_%=;\n\t"
        "bra.uni W0_%=;\n\t"
        "W1_%=:\n\t}"
        :: "r"(a), "r"(parity) : "memory");
}
__device__ __forceinline__ void bulk_g2s(uint32_t dst, const void* src,
                                         uint32_t bytes, uint32_t mbar) {
    asm volatile(
        "cp.async.bulk.shared::cluster.global.mbarrier::complete_tx::bytes "
        "[%0], [%1], %2, [%3];"
        :: "r"(dst), "l"(src), "r"(bytes), "r"(mbar) : "memory");
}
__device__ __forceinline__ void ldsm4(uint32_t* r, uint32_t addr) {
    asm volatile("ldmatrix.sync.aligned.m8n8.x4.shared.b16 {%0,%1,%2,%3}, [%4];"
                 : "=r"(r[0]), "=r"(r[1]), "=r"(r[2]), "=r"(r[3]) : "r"(addr));
}
__device__ __forceinline__ void mma16816(float* c, const uint32_t* a, const uint32_t* b) {
    asm volatile("mma.sync.aligned.m16n8k16.row.col.f32.f16.f16.f32 "
                 "{%0,%1,%2,%3}, {%4,%5,%6,%7}, {%8,%9}, {%0,%1,%2,%3};"
                 : "+f"(c[0]), "+f"(c[1]), "+f"(c[2]), "+f"(c[3])
                 : "r"(a[0]), "r"(a[1]), "r"(a[2]), "r"(a[3]),
                   "r"(b[0]), "r"(b[1]));
}

// ---------------------------------------------------------------------------
// Persistent GEMM. 288 threads: warps 0-7 compute (64x64 each), warp 8 producer.
// full[st]: tx barrier. empty[st]: 8 compute-warp arrivals.
// ---------------------------------------------------------------------------
__global__ __launch_bounds__(288, 1)
void gemm_hmma_kernel(const float* __restrict__ bias, float* __restrict__ C) {
    extern __shared__ char smem[];
    uint32_t sb = smem_u32(smem);
    int tid = threadIdx.x, wid = tid >> 5, lane = tid & 31;
    int p = blockIdx.x, P = gridDim.x;

    if (tid == 0) {
#pragma unroll
        for (int st = 0; st < NST; st++) {
            mbar_init(sb + st * 8, 1);            // full[st]
            mbar_init(sb + 64 + st * 8, 8);       // empty[st]
        }
    }
    __syncthreads();

    int ntiles = (NTILES - p + P - 1) / P;
    int GI = ntiles * KT;

    if (wid == 8) {
        // ---------------- producer warp ----------------
        if (lane == 0) {
            for (int f = 0; f < GI; f++) {
                int st = f & (NST - 1);
                if (f >= NST) mbar_wait(sb + 64 + st * 8, ((f >> 2) - 1) & 1);
                int tile = p + (f >> 6) * P;
                int ktf = f & 63;
                int mbf = tile & 31, nbf = tile >> 5;
                uint32_t fb = sb + st * 8;
                mbar_expect_tx(fb, STAGE_BYTES);
                uint32_t sdst = sb + SMEM_OFF + st * STAGE_BYTES;
                bulk_g2s(sdst, (const char*)g_Apack + (size_t)(mbf * 64 + ktf) * A_TILE,
                         A_TILE, fb);
                bulk_g2s(sdst + A_TILE,
                         (const char*)g_Bpack + (size_t)(nbf * 64 + ktf) * B_TILE,
                         B_TILE, fb);
            }
        }
        return;
    }

    // ---------------- compute warps ----------------
    int g = lane >> 3, tr = lane & 7;
    int m_warp = (wid & 1) * 64;
    int n_warp = (wid >> 1) * 64;
    int aRow0 = m_warp + (g & 1) * 8 + tr;
    int aH = g >> 1;
    int bRow0 = n_warp + (g >> 1) * 8 + tr;
    int bH = g & 1;

    for (int tile_i = 0; tile_i < ntiles; tile_i++) {
        int tile = p + tile_i * P;
        int mb = tile & 31, nb = tile >> 5;

        float acc[4][8][4];
#pragma unroll
        for (int i = 0; i < 4; i++)
#pragma unroll
            for (int j = 0; j < 8; j++)
#pragma unroll
                for (int k = 0; k < 4; k++) acc[i][j][k] = 0.f;

        for (int kt = 0; kt < KT; kt++) {
            int gi = tile_i * KT + kt;
            int st = gi & (NST - 1);
            mbar_wait(sb + st * 8, (gi >> 2) & 1);
            uint32_t As = sb + SMEM_OFF + st * STAGE_BYTES;
            uint32_t Bs = As + A_TILE;

            uint32_t af[2][4][4], bf[2][8][2];

            // load ks = 0 into buffer 0
            {
#pragma unroll
                for (int mt = 0; mt < 4; mt++) {
                    int r = aRow0 + mt * 16;
                    ldsm4(af[0][mt], As + r * 128 + (aH ^ (r & 7)) * 16);
                }
#pragma unroll
                for (int nt2 = 0; nt2 < 4; nt2++) {
                    int r = bRow0 + nt2 * 16;
                    uint32_t q[4];
                    ldsm4(q, Bs + r * 128 + (bH ^ (r & 7)) * 16);
                    bf[0][nt2 * 2][0] = q[0]; bf[0][nt2 * 2][1] = q[1];
                    bf[0][nt2 * 2 + 1][0] = q[2]; bf[0][nt2 * 2 + 1][1] = q[3];
                }
            }

#pragma unroll
            for (int ks = 0; ks < 4; ks++) {
                int cur = ks & 1, nxt = cur ^ 1;
                if (ks < 3) {
                    int kc = 2 * (ks + 1);
#pragma unroll
                    for (int mt = 0; mt < 4; mt++) {
                        int r = aRow0 + mt * 16;
                        ldsm4(af[nxt][mt], As + r * 128 + ((kc + aH) ^ (r & 7)) * 16);
                    }
#pragma unroll
                    for (int nt2 = 0; nt2 < 4; nt2++) {
                        int r = bRow0 + nt2 * 16;
                        uint32_t q[4];
                        ldsm4(q, Bs + r * 128 + ((kc + bH) ^ (r & 7)) * 16);
                        bf[nxt][nt2 * 2][0] = q[0]; bf[nxt][nt2 * 2][1] = q[1];
                        bf[nxt][nt2 * 2 + 1][0] = q[2]; bf[nxt][nt2 * 2 + 1][1] = q[3];
                    }
                } else if (lane == 0) {
                    mbar_arrive(sb + 64 + st * 8);    // stage fully read
                }
#pragma unroll
                for (int mt = 0; mt < 4; mt++)
#pragma unroll
                    for (int nt = 0; nt < 8; nt++)
                        mma16816(acc[mt][nt], af[cur][mt], bf[cur][nt]);
            }
        }

        // epilogue: registers -> gmem (+bias); stage smem untouched
        int m0 = mb * BM + m_warp;
        int n0 = nb * BN + n_warp;
        float2 bv[8];
#pragma unroll
        for (int nt = 0; nt < 8; nt++)
            bv[nt] = *reinterpret_cast<const float2*>(
                &bias[n0 + nt * 8 + (lane & 3) * 2]);
#pragma unroll
        for (int mt = 0; mt < 4; mt++) {
#pragma unroll
            for (int nt = 0; nt < 8; nt++) {
                int row = m0 + mt * 16 + (lane >> 2);
                int col = n0 + nt * 8 + (lane & 3) * 2;
                float2 v0 = make_float2(acc[mt][nt][0] + bv[nt].x,
                                        acc[mt][nt][1] + bv[nt].y);
                float2 v1 = make_float2(acc[mt][nt][2] + bv[nt].x,
                                        acc[mt][nt][3] + bv[nt].y);
                *reinterpret_cast<float2*>(&C[(size_t)row * N_DIM + col]) = v0;
                *reinterpret_cast<float2*>(&C[(size_t)(row + 8) * N_DIM + col]) = v1;
            }
        }
    }
}

// ---------------------------------------------------------------------------
// Launch
// ---------------------------------------------------------------------------
extern "C" void kernel_launch(void* const* d_in, const int* in_sizes, int n_in,
                              void* d_out, int out_size) {
    const float* A    = (const float*)d_in[0];
    const int*   B    = (const int*)  d_in[1];
    const float* s    = (const float*)d_in[2];
    const float* bias = (const float*)d_in[3];
    float* C = (float*)d_out;

    cudaFuncSetAttribute(gemm_hmma_kernel,
                         cudaFuncAttributeMaxDynamicSharedMemorySize, SMEM_BYTES);

    int nsm = 148;
    cudaDeviceGetAttribute(&nsm, cudaDevAttrMultiProcessorCount, 0);

    convA_kernel<<<(M_DIM * 512) / 256, 256>>>(A);
    dequant_kernel<<<((K_DIM / 16) * N_DIM) / 256, 256>>>(B, s);
    gemm_hmma_kernel<<<nsm, 288, SMEM_BYTES>>>(bias, C);
}

// round 8
// speedup vs baseline: 1.0370x; 1.0370x over previous
#include <cuda_runtime.h>
#include <cuda_fp16.h>
#include <cstdint>

#define M_DIM 4096
#define K_DIM 4096
#define N_DIM 12288

// GEMM tiling (round-6 proven config)
constexpr int BM = 128, BN = 256, BK = 32;
constexpr int KT = K_DIM / BK;                 // 128 k-tiles per output tile
constexpr int NTILES = (M_DIM / BM) * (N_DIM / BN);   // 1536
constexpr int NST = 8;                         // pipeline stages
constexpr int A_TILE = BM * BK * 2;            // 8192 B
constexpr int B_TILE = BN * BK * 2;            // 16384 B
constexpr int STAGE_BYTES = A_TILE + B_TILE;   // 24576
constexpr int SMEM_OFF = 1024;
constexpr int SMEM_BYTES = SMEM_OFF + NST * STAGE_BYTES;   // 197632

// tile-packed, pre-swizzled operand blobs
__device__ __half g_Apack[(size_t)M_DIM * K_DIM];   // tiles (mb*128+kt): 128x32
__device__ __half g_Bpack[(size_t)N_DIM * K_DIM];   // tiles (nb*128+kt): 256x32 [n][k]

// chunk swizzle: 16B chunk c within 64B row r -> c ^ ((r>>1)&3)

// ---------------------------------------------------------------------------
// Pack A: fp32 [M,K] -> fp16 tiles, blob ((mb*128+kt) tiles of 8KB)
// ---------------------------------------------------------------------------
__global__ void convA_kernel(const float* __restrict__ A) {
    int id = blockIdx.x * 256 + threadIdx.x;    // M*512 16B-chunk ids
    int m = id >> 9;
    int ch = id & 511;
    int kt = ch >> 2, c = ch & 3;
    const float4* src = reinterpret_cast<const float4*>(
        A + (size_t)m * K_DIM + kt * 32 + c * 8);
    float4 v0 = src[0], v1 = src[1];
    __half2 h[4];
    h[0] = __floats2half2_rn(v0.x, v0.y);
    h[1] = __floats2half2_rn(v0.z, v0.w);
    h[2] = __floats2half2_rn(v1.x, v1.y);
    h[3] = __floats2half2_rn(v1.z, v1.w);
    int mb = m >> 7, r = m & 127;
    int cs = c ^ ((r >> 1) & 3);
    char* dst = (char*)g_Apack + (size_t)(mb * 128 + kt) * A_TILE + r * 64 + cs * 16;
    *reinterpret_cast<uint4*>(dst) = *reinterpret_cast<uint4*>(h);
}

// ---------------------------------------------------------------------------
// Dequant+pack W: int4 -> fp16 [n][k] tiles, blob ((nb*128+kt) tiles of 16KB)
// ---------------------------------------------------------------------------
__global__ void dequant_kernel(const int* __restrict__ B, const float* __restrict__ s) {
    int id = blockIdx.x * 256 + threadIdx.x;    // (K/16)*N ids
    int t = id / N_DIM, o = id - t * N_DIM;
    int2 p = reinterpret_cast<const int2*>(B)[(size_t)t * N_DIM + o];
    float sc = s[(t >> 3) * N_DIM + o];
    __half2 h[8];
#pragma unroll
    for (int c8 = 0; c8 < 2; c8++) {
        int v = c8 ? p.y : p.x;
#pragma unroll
        for (int j = 0; j < 4; j++) {
            float w0 = (float)(((v >> (8 * j)) & 0xF) - 8) * sc;
            float w1 = (float)(((v >> (8 * j + 4)) & 0xF) - 8) * sc;
            h[c8 * 4 + j] = __floats2half2_rn(w0, w1);
        }
    }
    int kt = t >> 1;
    int nb = o >> 8, r = o & 255;
    char* tile = (char*)g_Bpack + (size_t)(nb * 128 + kt) * B_TILE;
    int c0 = 2 * (t & 1);
    int xm = (r >> 1) & 3;
    *reinterpret_cast<uint4*>(tile + r * 64 + (c0 ^ xm) * 16)       = *reinterpret_cast<uint4*>(h);
    *reinterpret_cast<uint4*>(tile + r * 64 + ((c0 + 1) ^ xm) * 16) = *reinterpret_cast<uint4*>(h + 4);
}

// ---------------------------------------------------------------------------
// helpers
// ---------------------------------------------------------------------------
__device__ __forceinline__ uint32_t smem_u32(const void* p) {
    return (uint32_t)__cvta_generic_to_shared(p);
}
__device__ __forceinline__ void mbar_init(uint32_t a, uint32_t cnt) {
    asm volatile("mbarrier.init.shared.b64 [%0], %1;" :: "r"(a), "r"(cnt) : "memory");
}
__device__ __forceinline__ void mbar_expect_tx(uint32_t a, uint32_t bytes) {
    asm volatile("mbarrier.arrive.expect_tx.shared.b64 _, [%0], %1;"
                 :: "r"(a), "r"(bytes) : "memory");
}
__device__ __forceinline__ void mbar_arrive(uint32_t a) {
    asm volatile("mbarrier.arrive.shared.b64 _, [%0];" :: "r"(a) : "memory");
}
__device__ __forceinline__ void mbar_wait(uint32_t a, uint32_t parity) {
    asm volatile(
        "{\n\t.reg .pred P;\n"
        "W0_%=:\n\t"
        "mbarrier.try_wait.parity.acquire.cta.shared::cta.b64 P, [%0], %1, 0x989680;\n\t"
        "@P bra.uni W1_%=;\n\t"
        "bra.uni W0_%=;\n\t"
        "W1_%=:\n\t}"
        :: "r"(a), "r"(parity) : "memory");
}
__device__ __forceinline__ void bulk_g2s(uint32_t dst, const void* src,
                                         uint32_t bytes, uint32_t mbar) {
    asm volatile(
        "cp.async.bulk.shared::cluster.global.mbarrier::complete_tx::bytes "
        "[%0], [%1], %2, [%3];"
        :: "r"(dst), "l"(src), "r"(bytes), "r"(mbar) : "memory");
}
__device__ __forceinline__ void ldsm4(uint32_t* r, uint32_t addr) {
    asm volatile("ldmatrix.sync.aligned.m8n8.x4.shared.b16 {%0,%1,%2,%3}, [%4];"
                 : "=r"(r[0]), "=r"(r[1]), "=r"(r[2]), "=r"(r[3]) : "r"(addr));
}
__device__ __forceinline__ void mma16816(float* c, const uint32_t* a, const uint32_t* b) {
    asm volatile("mma.sync.aligned.m16n8k16.row.col.f32.f16.f16.f32 "
                 "{%0,%1,%2,%3}, {%4,%5,%6,%7}, {%8,%9}, {%0,%1,%2,%3};"
                 : "+f"(c[0]), "+f"(c[1]), "+f"(c[2]), "+f"(c[3])
                 : "r"(a[0]), "r"(a[1]), "r"(a[2]), "r"(a[3]),
                   "r"(b[0]), "r"(b[1]));
}

// ---------------------------------------------------------------------------
// Persistent GEMM. 288 threads: warps 0-7 compute (64x64 each), warp 8 producer.
// full[st]: tx barrier (1). empty[st]: 8 compute-warp arrivals.
// SMSP pairs (w, w+4) process the two ks halves in OPPOSITE order so one
// warp's HMMA burst covers its partner's LDSM burst.
// ---------------------------------------------------------------------------
__global__ __launch_bounds__(288, 1)
void gemm_hmma_kernel(const float* __restrict__ bias, float* __restrict__ C) {
    extern __shared__ char smem[];
    uint32_t sb = smem_u32(smem);
    int tid = threadIdx.x, wid = tid >> 5, lane = tid & 31;
    int p = blockIdx.x, P = gridDim.x;

    if (tid == 0) {
#pragma unroll
        for (int st = 0; st < NST; st++) {
            mbar_init(sb + st * 8, 1);            // full[st]
            mbar_init(sb + 64 + st * 8, 8);       // empty[st]
        }
    }
    __syncthreads();

    int ntiles = (NTILES - p + P - 1) / P;
    int GI = ntiles * KT;

    if (wid == 8) {
        // ---------------- producer warp ----------------
        if (lane == 0) {
            for (int f = 0; f < GI; f++) {
                int st = f & (NST - 1);
                if (f >= NST) mbar_wait(sb + 64 + st * 8, ((f >> 3) - 1) & 1);
                int tile = p + (f >> 7) * P;
                int ktf = f & 127;
                int mbf = tile & 31, nbf = tile >> 5;
                uint32_t fb = sb + st * 8;
                mbar_expect_tx(fb, STAGE_BYTES);
                uint32_t sdst = sb + SMEM_OFF + st * STAGE_BYTES;
                bulk_g2s(sdst,
                         (const char*)g_Apack + (size_t)(mbf * 128 + ktf) * A_TILE,
                         A_TILE, fb);
                bulk_g2s(sdst + A_TILE,
                         (const char*)g_Bpack + (size_t)(nbf * 128 + ktf) * B_TILE,
                         B_TILE, fb);
            }
        }
        return;
    }

    // ---------------- compute warps ----------------
    int g = lane >> 3, tr = lane & 7;
    int m_warp = (wid & 1) * 64;
    int n_warp = (wid >> 1) * 64;
    int aRow0 = m_warp + (g & 1) * 8 + tr;
    int aH = g >> 1;
    int bRow0 = n_warp + (g >> 1) * 8 + tr;
    int bH = g & 1;
    int ord = (wid >> 2) & 1;                   // ks stagger for SMSP partner

    for (int tile_i = 0; tile_i < ntiles; tile_i++) {
        int tile = p + tile_i * P;
        int mb = tile & 31, nb = tile >> 5;

        float acc[4][8][4];
#pragma unroll
        for (int i = 0; i < 4; i++)
#pragma unroll
            for (int j = 0; j < 8; j++)
#pragma unroll
                for (int k = 0; k < 4; k++) acc[i][j][k] = 0.f;

        for (int kt = 0; kt < KT; kt++) {
            int gi = tile_i * KT + kt;
            int st = gi & (NST - 1);
            mbar_wait(sb + st * 8, (gi >> 3) & 1);
            uint32_t As = sb + SMEM_OFF + st * STAGE_BYTES;
            uint32_t Bs = As + A_TILE;

#pragma unroll
            for (int half = 0; half < 2; half++) {
                int ks = half ^ ord;            // opposite order on partner warp
                int kc = 2 * ks;
                uint32_t a0[4][4], b0[8][2];
#pragma unroll
                for (int mt = 0; mt < 4; mt++) {
                    int r = aRow0 + mt * 16;
                    int c = (kc + aH) ^ ((r >> 1) & 3);
                    ldsm4(a0[mt], As + r * 64 + c * 16);
                }
#pragma unroll
                for (int nt2 = 0; nt2 < 4; nt2++) {
                    int r = bRow0 + nt2 * 16;
                    int c = (kc + bH) ^ ((r >> 1) & 3);
                    uint32_t q[4];
                    ldsm4(q, Bs + r * 64 + c * 16);
                    b0[nt2 * 2][0] = q[0]; b0[nt2 * 2][1] = q[1];
                    b0[nt2 * 2 + 1][0] = q[2]; b0[nt2 * 2 + 1][1] = q[3];
                }
                if (half == 1 && lane == 0)
                    mbar_arrive(sb + 64 + st * 8);   // stage fully read
#pragma unroll
                for (int mt = 0; mt < 4; mt++)
#pragma unroll
                    for (int nt = 0; nt < 8; nt++)
                        mma16816(acc[mt][nt], a0[mt], b0[nt]);
            }
        }

        // epilogue: registers -> gmem (+bias); stage smem untouched
        int m0 = mb * BM + m_warp;
        int n0 = nb * BN + n_warp;
        float2 bv[8];
#pragma unroll
        for (int nt = 0; nt < 8; nt++)
            bv[nt] = *reinterpret_cast<const float2*>(
                &bias[n0 + nt * 8 + (lane & 3) * 2]);
#pragma unroll
        for (int mt = 0; mt < 4; mt++) {
#pragma unroll
            for (int nt = 0; nt < 8; nt++) {
                int row = m0 + mt * 16 + (lane >> 2);
                int col = n0 + nt * 8 + (lane & 3) * 2;
                float2 v0 = make_float2(acc[mt][nt][0] + bv[nt].x,
                                        acc[mt][nt][1] + bv[nt].y);
                float2 v1 = make_float2(acc[mt][nt][2] + bv[nt].x,
                                        acc[mt][nt][3] + bv[nt].y);
                *reinterpret_cast<float2*>(&C[(size_t)row * N_DIM + col]) = v0;
                *reinterpret_cast<float2*>(&C[(size_t)(row + 8) * N_DIM + col]) = v1;
            }
        }
    }
}

// ---------------------------------------------------------------------------
// Launch
// ---------------------------------------------------------------------------
extern "C" void kernel_launch(void* const* d_in, const int* in_sizes, int n_in,
                              void* d_out, int out_size) {
    const float* A    = (const float*)d_in[0];
    const int*   B    = (const int*)  d_in[1];
    const float* s    = (const float*)d_in[2];
    const float* bias = (const float*)d_in[3];
    float* C = (float*)d_out;

    cudaFuncSetAttribute(gemm_hmma_kernel,
                         cudaFuncAttributeMaxDynamicSharedMemorySize, SMEM_BYTES);

    int nsm = 148;
    cudaDeviceGetAttribute(&nsm, cudaDevAttrMultiProcessorCount, 0);

    convA_kernel<<<(M_DIM * 512) / 256, 256>>>(A);
    dequant_kernel<<<((K_DIM / 16) * N_DIM) / 256, 256>>>(B, s);
    gemm_hmma_kernel<<<nsm, 288, SMEM_BYTES>>>(bias, C);
}

// round 9
// speedup vs baseline: 1.0556x; 1.0179x over previous
#include <cuda_runtime.h>
#include <cuda_fp16.h>
#include <cstdint>

#define M_DIM 4096
#define K_DIM 4096
#define N_DIM 12288

// GEMM tiling (R6 pipeline, 16 compute warps of 32x64)
constexpr int BM = 128, BN = 256, BK = 32;
constexpr int KT = K_DIM / BK;                 // 128 k-tiles per output tile
constexpr int NTILES = (M_DIM / BM) * (N_DIM / BN);   // 1536
constexpr int NST = 8;                         // pipeline stages
constexpr int A_TILE = BM * BK * 2;            // 8192 B
constexpr int B_TILE = BN * BK * 2;            // 16384 B
constexpr int STAGE_BYTES = A_TILE + B_TILE;   // 24576
constexpr int SMEM_OFF = 1024;
constexpr int SMEM_BYTES = SMEM_OFF + NST * STAGE_BYTES;   // 197632
constexpr int NWARPS = 16;

// tile-packed, pre-swizzled operand blobs
__device__ __half g_Apack[(size_t)M_DIM * K_DIM];   // tiles (mb*128+kt): 128x32
__device__ __half g_Bpack[(size_t)N_DIM * K_DIM];   // tiles (nb*128+kt): 256x32 [n][k]

// chunk swizzle: 16B chunk c within 64B row r -> c ^ ((r>>1)&3)

// ---------------------------------------------------------------------------
// Pack A: fp32 [M,K] -> fp16 tiles, blob ((mb*128+kt) tiles of 8KB)
// ---------------------------------------------------------------------------
__global__ void convA_kernel(const float* __restrict__ A) {
    int id = blockIdx.x * 256 + threadIdx.x;    // M*512 16B-chunk ids
    int m = id >> 9;
    int ch = id & 511;
    int kt = ch >> 2, c = ch & 3;
    const float4* src = reinterpret_cast<const float4*>(
        A + (size_t)m * K_DIM + kt * 32 + c * 8);
    float4 v0 = src[0], v1 = src[1];
    __half2 h[4];
    h[0] = __floats2half2_rn(v0.x, v0.y);
    h[1] = __floats2half2_rn(v0.z, v0.w);
    h[2] = __floats2half2_rn(v1.x, v1.y);
    h[3] = __floats2half2_rn(v1.z, v1.w);
    int mb = m >> 7, r = m & 127;
    int cs = c ^ ((r >> 1) & 3);
    char* dst = (char*)g_Apack + (size_t)(mb * 128 + kt) * A_TILE + r * 64 + cs * 16;
    *reinterpret_cast<uint4*>(dst) = *reinterpret_cast<uint4*>(h);
}

// ---------------------------------------------------------------------------
// Dequant+pack W: int4 -> fp16 [n][k] tiles, blob ((nb*128+kt) tiles of 16KB)
// ---------------------------------------------------------------------------
__global__ void dequant_kernel(const int* __restrict__ B, const float* __restrict__ s) {
    int id = blockIdx.x * 256 + threadIdx.x;    // (K/16)*N ids
    int t = id / N_DIM, o = id - t * N_DIM;
    int2 p = reinterpret_cast<const int2*>(B)[(size_t)t * N_DIM + o];
    float sc = s[(t >> 3) * N_DIM + o];
    __half2 h[8];
#pragma unroll
    for (int c8 = 0; c8 < 2; c8++) {
        int v = c8 ? p.y : p.x;
#pragma unroll
        for (int j = 0; j < 4; j++) {
            float w0 = (float)(((v >> (8 * j)) & 0xF) - 8) * sc;
            float w1 = (float)(((v >> (8 * j + 4)) & 0xF) - 8) * sc;
            h[c8 * 4 + j] = __floats2half2_rn(w0, w1);
        }
    }
    int kt = t >> 1;
    int nb = o >> 8, r = o & 255;
    char* tile = (char*)g_Bpack + (size_t)(nb * 128 + kt) * B_TILE;
    int c0 = 2 * (t & 1);
    int xm = (r >> 1) & 3;
    *reinterpret_cast<uint4*>(tile + r * 64 + (c0 ^ xm) * 16)       = *reinterpret_cast<uint4*>(h);
    *reinterpret_cast<uint4*>(tile + r * 64 + ((c0 + 1) ^ xm) * 16) = *reinterpret_cast<uint4*>(h + 4);
}

// ---------------------------------------------------------------------------
// helpers
// ---------------------------------------------------------------------------
__device__ __forceinline__ uint32_t smem_u32(const void* p) {
    return (uint32_t)__cvta_generic_to_shared(p);
}
__device__ __forceinline__ void mbar_init(uint32_t a, uint32_t cnt) {
    asm volatile("mbarrier.init.shared.b64 [%0], %1;" :: "r"(a), "r"(cnt) : "memory");
}
__device__ __forceinline__ void mbar_expect_tx(uint32_t a, uint32_t bytes) {
    asm volatile("mbarrier.arrive.expect_tx.shared.b64 _, [%0], %1;"
                 :: "r"(a), "r"(bytes) : "memory");
}
__device__ __forceinline__ void mbar_arrive(uint32_t a) {
    asm volatile("mbarrier.arrive.shared.b64 _, [%0];" :: "r"(a) : "memory");
}
__device__ __forceinline__ void mbar_wait(uint32_t a, uint32_t parity) {
    asm volatile(
        "{\n\t.reg .pred P;\n"
        "W0_%=:\n\t"
        "mbarrier.try_wait.parity.acquire.cta.shared::cta.b64 P, [%0], %1, 0x989680;\n\t"
        "@P bra.uni W1_%=;\n\t"
        "bra.uni W0_%=;\n\t"
        "W1_%=:\n\t}"
        :: "r"(a), "r"(parity) : "memory");
}
__device__ __forceinline__ void bulk_g2s(uint32_t dst, const void* src,
                                         uint32_t bytes, uint32_t mbar) {
    asm volatile(
        "cp.async.bulk.shared::cluster.global.mbarrier::complete_tx::bytes "
        "[%0], [%1], %2, [%3];"
        :: "r"(dst), "l"(src), "r"(bytes), "r"(mbar) : "memory");
}
__device__ __forceinline__ void ldsm4(uint32_t* r, uint32_t addr) {
    asm volatile("ldmatrix.sync.aligned.m8n8.x4.shared.b16 {%0,%1,%2,%3}, [%4];"
                 : "=r"(r[0]), "=r"(r[1]), "=r"(r[2]), "=r"(r[3]) : "r"(addr));
}
__device__ __forceinline__ void mma16816(float* c, const uint32_t* a, const uint32_t* b) {
    asm volatile("mma.sync.aligned.m16n8k16.row.col.f32.f16.f16.f32 "
                 "{%0,%1,%2,%3}, {%4,%5,%6,%7}, {%8,%9}, {%0,%1,%2,%3};"
                 : "+f"(c[0]), "+f"(c[1]), "+f"(c[2]), "+f"(c[3])
                 : "r"(a[0]), "r"(a[1]), "r"(a[2]), "r"(a[3]),
                   "r"(b[0]), "r"(b[1]));
}

// ---------------------------------------------------------------------------
// Persistent GEMM. 512 threads = 16 compute warps (32x64 tiles, 4/SMSP).
// full[st]: tx barrier. empty[st]: 16 warp arrivals. Inline tid==0 producer.
// ---------------------------------------------------------------------------
__global__ __launch_bounds__(512, 1)
void gemm_hmma_kernel(const float* __restrict__ bias, float* __restrict__ C) {
    extern __shared__ char smem[];
    uint32_t sb = smem_u32(smem);
    int tid = threadIdx.x, wid = tid >> 5, lane = tid & 31;
    int p = blockIdx.x, P = gridDim.x;

    if (tid == 0) {
#pragma unroll
        for (int st = 0; st < NST; st++) {
            mbar_init(sb + st * 8, 1);             // full[st]
            mbar_init(sb + 64 + st * 8, NWARPS);   // empty[st]
        }
    }
    __syncthreads();

    int ntiles = (NTILES - p + P - 1) / P;
    int GI = ntiles * KT;

    // producer: fill global iteration f's stage (inline in warp 0 lane 0)
    auto fill = [&](int f) {
        int st = f & (NST - 1);
        if (f >= NST) mbar_wait(sb + 64 + st * 8, ((f >> 3) - 1) & 1);
        int tile = p + (f >> 7) * P;
        int ktf = f & 127;
        int mbf = tile & 31, nbf = tile >> 5;
        uint32_t fb = sb + st * 8;
        mbar_expect_tx(fb, STAGE_BYTES);
        uint32_t sdst = sb + SMEM_OFF + st * STAGE_BYTES;
        bulk_g2s(sdst, (const char*)g_Apack + (size_t)(mbf * 128 + ktf) * A_TILE,
                 A_TILE, fb);
        bulk_g2s(sdst + A_TILE,
                 (const char*)g_Bpack + (size_t)(nbf * 128 + ktf) * B_TILE,
                 B_TILE, fb);
    };
    if (tid == 0) {
        for (int f = 0; f < NST && f < GI; f++) fill(f);
    }

    // per-thread ldmatrix geometry (warp tile 32x64: 4 m-pos x 4 n-pos)
    int g = lane >> 3, tr = lane & 7;
    int m_warp = (wid & 3) * 32;
    int n_warp = (wid >> 2) * 64;
    int aRow0 = m_warp + (g & 1) * 8 + tr;
    int aH = g >> 1;
    int bRow0 = n_warp + (g >> 1) * 8 + tr;
    int bH = g & 1;

    for (int tile_i = 0; tile_i < ntiles; tile_i++) {
        int tile = p + tile_i * P;
        int mb = tile & 31, nb = tile >> 5;

        float acc[2][8][4];
#pragma unroll
        for (int i = 0; i < 2; i++)
#pragma unroll
            for (int j = 0; j < 8; j++)
#pragma unroll
                for (int k = 0; k < 4; k++) acc[i][j][k] = 0.f;

        for (int kt = 0; kt < KT; kt++) {
            int gi = tile_i * KT + kt;
            int st = gi & (NST - 1);
            mbar_wait(sb + st * 8, (gi >> 3) & 1);
            uint32_t As = sb + SMEM_OFF + st * STAGE_BYTES;
            uint32_t Bs = As + A_TILE;

#pragma unroll
            for (int ks = 0; ks < 2; ks++) {
                int kc = 2 * ks;
                uint32_t a0[2][4], b0[8][2];
#pragma unroll
                for (int mt = 0; mt < 2; mt++) {
                    int r = aRow0 + mt * 16;
                    int c = (kc + aH) ^ ((r >> 1) & 3);
                    ldsm4(a0[mt], As + r * 64 + c * 16);
                }
#pragma unroll
                for (int nt2 = 0; nt2 < 4; nt2++) {
                    int r = bRow0 + nt2 * 16;
                    int c = (kc + bH) ^ ((r >> 1) & 3);
                    uint32_t q[4];
                    ldsm4(q, Bs + r * 64 + c * 16);
                    b0[nt2 * 2][0] = q[0]; b0[nt2 * 2][1] = q[1];
                    b0[nt2 * 2 + 1][0] = q[2]; b0[nt2 * 2 + 1][1] = q[3];
                }
                if (ks == 1 && lane == 0)
                    mbar_arrive(sb + 64 + st * 8);   // stage fully read
#pragma unroll
                for (int mt = 0; mt < 2; mt++)
#pragma unroll
                    for (int nt = 0; nt < 8; nt++)
                        mma16816(acc[mt][nt], a0[mt], b0[nt]);
            }

            if (tid == 0) {
                int f = gi + NST;
                if (f < GI) fill(f);
            }
        }

        // epilogue: registers -> gmem (+bias); stage smem untouched
        int m0 = mb * BM + m_warp;
        int n0 = nb * BN + n_warp;
        float2 bv[8];
#pragma unroll
        for (int nt = 0; nt < 8; nt++)
            bv[nt] = *reinterpret_cast<const float2*>(
                &bias[n0 + nt * 8 + (lane & 3) * 2]);
#pragma unroll
        for (int mt = 0; mt < 2; mt++) {
#pragma unroll
            for (int nt = 0; nt < 8; nt++) {
                int row = m0 + mt * 16 + (lane >> 2);
                int col = n0 + nt * 8 + (lane & 3) * 2;
                float2 v0 = make_float2(acc[mt][nt][0] + bv[nt].x,
                                        acc[mt][nt][1] + bv[nt].y);
                float2 v1 = make_float2(acc[mt][nt][2] + bv[nt].x,
                                        acc[mt][nt][3] + bv[nt].y);
                *reinterpret_cast<float2*>(&C[(size_t)row * N_DIM + col]) = v0;
                *reinterpret_cast<float2*>(&C[(size_t)(row + 8) * N_DIM + col]) = v1;
            }
        }
    }
}

// ---------------------------------------------------------------------------
// Launch
// ---------------------------------------------------------------------------
extern "C" void kernel_launch(void* const* d_in, const int* in_sizes, int n_in,
                              void* d_out, int out_size) {
    const float* A    = (const float*)d_in[0];
    const int*   B    = (const int*)  d_in[1];
    const float* s    = (const float*)d_in[2];
    const float* bias = (const float*)d_in[3];
    float* C = (float*)d_out;

    cudaFuncSetAttribute(gemm_hmma_kernel,
                         cudaFuncAttributeMaxDynamicSharedMemorySize, SMEM_BYTES);

    int nsm = 148;
    cudaDeviceGetAttribute(&nsm, cudaDevAttrMultiProcessorCount, 0);

    convA_kernel<<<(M_DIM * 512) / 256, 256>>>(A);
    dequant_kernel<<<((K_DIM / 16) * N_DIM) / 256, 256>>>(B, s);
    gemm_hmma_kernel<<<nsm, 512, SMEM_BYTES>>>(bias, C);
}

// round 10
// speedup vs baseline: 1.1412x; 1.0812x over previous
#include <cuda_runtime.h>
#include <cuda_fp16.h>
#include <cstdint>

#define M_DIM 4096
#define K_DIM 4096
#define N_DIM 12288

// GEMM tiling (R6 proven config)
constexpr int BM = 128, BN = 256, BK = 32;
constexpr int KT = K_DIM / BK;                 // 128 k-tiles per output tile
constexpr int NTILES = (M_DIM / BM) * (N_DIM / BN);   // 1536
constexpr int NST = 8;                         // pipeline stages
constexpr int A_TILE = BM * BK * 2;            // 8192 B
constexpr int B_TILE = BN * BK * 2;            // 16384 B
constexpr int STAGE_BYTES = A_TILE + B_TILE;   // 24576
constexpr int SMEM_OFF = 1024;
constexpr int SMEM_BYTES = SMEM_OFF + NST * STAGE_BYTES;   // 197632

// tile-packed, pre-swizzled operand blobs
__device__ __half g_Apack[(size_t)M_DIM * K_DIM];   // tiles (mb*128+kt): 128x32
__device__ __half g_Bpack[(size_t)N_DIM * K_DIM];   // tiles (nb*128+kt): 256x32 [n][k]

// chunk swizzle: 16B chunk c within 64B row r -> c ^ ((r>>1)&3)

// ---------------------------------------------------------------------------
// Pack A: fp32 [M,K] -> fp16 tiles, blob ((mb*128+kt) tiles of 8KB)
// ---------------------------------------------------------------------------
__global__ void convA_kernel(const float* __restrict__ A) {
    int id = blockIdx.x * 256 + threadIdx.x;    // M*512 16B-chunk ids
    int m = id >> 9;
    int ch = id & 511;
    int kt = ch >> 2, c = ch & 3;
    const float4* src = reinterpret_cast<const float4*>(
        A + (size_t)m * K_DIM + kt * 32 + c * 8);
    float4 v0 = src[0], v1 = src[1];
    __half2 h[4];
    h[0] = __floats2half2_rn(v0.x, v0.y);
    h[1] = __floats2half2_rn(v0.z, v0.w);
    h[2] = __floats2half2_rn(v1.x, v1.y);
    h[3] = __floats2half2_rn(v1.z, v1.w);
    int mb = m >> 7, r = m & 127;
    int cs = c ^ ((r >> 1) & 3);
    char* dst = (char*)g_Apack + (size_t)(mb * 128 + kt) * A_TILE + r * 64 + cs * 16;
    *reinterpret_cast<uint4*>(dst) = *reinterpret_cast<uint4*>(h);
}

// ---------------------------------------------------------------------------
// Dequant+pack W: int4 -> fp16 [n][k] tiles, blob ((nb*128+kt) tiles of 16KB)
// ---------------------------------------------------------------------------
__global__ void dequant_kernel(const int* __restrict__ B, const float* __restrict__ s) {
    int id = blockIdx.x * 256 + threadIdx.x;    // (K/16)*N ids
    int t = id / N_DIM, o = id - t * N_DIM;
    int2 p = reinterpret_cast<const int2*>(B)[(size_t)t * N_DIM + o];
    float sc = s[(t >> 3) * N_DIM + o];
    __half2 h[8];
#pragma unroll
    for (int c8 = 0; c8 < 2; c8++) {
        int v = c8 ? p.y : p.x;
#pragma unroll
        for (int j = 0; j < 4; j++) {
            float w0 = (float)(((v >> (8 * j)) & 0xF) - 8) * sc;
            float w1 = (float)(((v >> (8 * j + 4)) & 0xF) - 8) * sc;
            h[c8 * 4 + j] = __floats2half2_rn(w0, w1);
        }
    }
    int kt = t >> 1;
    int nb = o >> 8, r = o & 255;
    char* tile = (char*)g_Bpack + (size_t)(nb * 128 + kt) * B_TILE;
    int c0 = 2 * (t & 1);
    int xm = (r >> 1) & 3;
    *reinterpret_cast<uint4*>(tile + r * 64 + (c0 ^ xm) * 16)       = *reinterpret_cast<uint4*>(h);
    *reinterpret_cast<uint4*>(tile + r * 64 + ((c0 + 1) ^ xm) * 16) = *reinterpret_cast<uint4*>(h + 4);
}

// ---------------------------------------------------------------------------
// helpers
// ---------------------------------------------------------------------------
__device__ __forceinline__ uint32_t smem_u32(const void* p) {
    return (uint32_t)__cvta_generic_to_shared(p);
}
__device__ __forceinline__ void mbar_init(uint32_t a, uint32_t cnt) {
    asm volatile("mbarrier.init.shared.b64 [%0], %1;" :: "r"(a), "r"(cnt) : "memory");
}
__device__ __forceinline__ void mbar_expect_tx(uint32_t a, uint32_t bytes) {
    asm volatile("mbarrier.arrive.expect_tx.shared.b64 _, [%0], %1;"
                 :: "r"(a), "r"(bytes) : "memory");
}
__device__ __forceinline__ void mbar_arrive(uint32_t a) {
    asm volatile("mbarrier.arrive.shared.b64 _, [%0];" :: "r"(a) : "memory");
}
__device__ __forceinline__ void mbar_wait(uint32_t a, uint32_t parity) {
    asm volatile(
        "{\n\t.reg .pred P;\n"
        "W0_%=:\n\t"
        "mbarrier.try_wait.parity.acquire.cta.shared::cta.b64 P, [%0], %1, 0x989680;\n\t"
        "@P bra.uni W1_%=;\n\t"
        "bra.uni W0_%=;\n\t"
        "W1_%=:\n\t}"
        :: "r"(a), "r"(parity) : "memory");
}
__device__ __forceinline__ void bulk_g2s(uint32_t dst, const void* src,
                                         uint32_t bytes, uint32_t mbar) {
    asm volatile(
        "cp.async.bulk.shared::cluster.global.mbarrier::complete_tx::bytes "
        "[%0], [%1], %2, [%3];"
        :: "r"(dst), "l"(src), "r"(bytes), "r"(mbar) : "memory");
}
__device__ __forceinline__ void ldsm4(uint32_t* r, uint32_t addr) {
    asm volatile("ldmatrix.sync.aligned.m8n8.x4.shared.b16 {%0,%1,%2,%3}, [%4];"
                 : "=r"(r[0]), "=r"(r[1]), "=r"(r[2]), "=r"(r[3]) : "r"(addr));
}
__device__ __forceinline__ void mma16816(float* c, const uint32_t* a, const uint32_t* b) {
    asm volatile("mma.sync.aligned.m16n8k16.row.col.f32.f16.f16.f32 "
                 "{%0,%1,%2,%3}, {%4,%5,%6,%7}, {%8,%9}, {%0,%1,%2,%3};"
                 : "+f"(c[0]), "+f"(c[1]), "+f"(c[2]), "+f"(c[3])
                 : "r"(a[0]), "r"(a[1]), "r"(a[2]), "r"(a[3]),
                   "r"(b[0]), "r"(b[1]));
}

// ---------------------------------------------------------------------------
// Persistent GEMM. 256 threads = 8 compute warps (64x64). Distributed fill:
// warp (gi&7) lane 0 refills iteration gi+NST. Fine-grain LDSM/MMA interleave.
// full[st]: tx barrier (1). empty[st]: 8 warp arrivals.
// ---------------------------------------------------------------------------
__global__ __launch_bounds__(256, 1)
void gemm_hmma_kernel(const float* __restrict__ bias, float* __restrict__ C) {
    extern __shared__ char smem[];
    uint32_t sb = smem_u32(smem);
    int tid = threadIdx.x, wid = tid >> 5, lane = tid & 31;
    int p = blockIdx.x, P = gridDim.x;

    if (tid == 0) {
#pragma unroll
        for (int st = 0; st < NST; st++) {
            mbar_init(sb + st * 8, 1);            // full[st]
            mbar_init(sb + 64 + st * 8, 8);       // empty[st]
        }
    }
    __syncthreads();

    int ntiles = (NTILES - p + P - 1) / P;
    int GI = ntiles * KT;

    // fill global iteration f's stage
    auto fill = [&](int f) {
        int st = f & (NST - 1);
        if (f >= NST) mbar_wait(sb + 64 + st * 8, ((f >> 3) - 1) & 1);
        int tile = p + (f >> 7) * P;
        int ktf = f & 127;
        int mbf = tile & 31, nbf = tile >> 5;
        uint32_t fb = sb + st * 8;
        mbar_expect_tx(fb, STAGE_BYTES);
        uint32_t sdst = sb + SMEM_OFF + st * STAGE_BYTES;
        bulk_g2s(sdst, (const char*)g_Apack + (size_t)(mbf * 128 + ktf) * A_TILE,
                 A_TILE, fb);
        bulk_g2s(sdst + A_TILE,
                 (const char*)g_Bpack + (size_t)(nbf * 128 + ktf) * B_TILE,
                 B_TILE, fb);
    };
    if (tid == 0) {
        for (int f = 0; f < NST && f < GI; f++) fill(f);
    }

    // per-thread ldmatrix geometry (warp tile 64x64)
    int g = lane >> 3, tr = lane & 7;
    int m_warp = (wid & 1) * 64;
    int n_warp = (wid >> 1) * 64;
    int aRow0 = m_warp + (g & 1) * 8 + tr;
    int aH = g >> 1;
    int bRow0 = n_warp + (g >> 1) * 8 + tr;
    int bH = g & 1;

    for (int tile_i = 0; tile_i < ntiles; tile_i++) {
        int tile = p + tile_i * P;
        int mb = tile & 31, nb = tile >> 5;

        float acc[4][8][4];
#pragma unroll
        for (int i = 0; i < 4; i++)
#pragma unroll
            for (int j = 0; j < 8; j++)
#pragma unroll
                for (int k = 0; k < 4; k++) acc[i][j][k] = 0.f;

        for (int kt = 0; kt < KT; kt++) {
            int gi = tile_i * KT + kt;
            int st = gi & (NST - 1);
            mbar_wait(sb + st * 8, (gi >> 3) & 1);
            uint32_t As = sb + SMEM_OFF + st * STAGE_BYTES;
            uint32_t Bs = As + A_TILE;

#pragma unroll
            for (int ks = 0; ks < 2; ks++) {
                int kc = 2 * ks;
                uint32_t a0[4][4];
#pragma unroll
                for (int mt = 0; mt < 4; mt++) {
                    int r = aRow0 + mt * 16;
                    int c = (kc + aH) ^ ((r >> 1) & 3);
                    ldsm4(a0[mt], As + r * 64 + c * 16);
                }
                // interleave: one B ldsm, then its 8 MMAs
#pragma unroll
                for (int nt2 = 0; nt2 < 4; nt2++) {
                    int r = bRow0 + nt2 * 16;
                    int c = (kc + bH) ^ ((r >> 1) & 3);
                    uint32_t q[4];
                    ldsm4(q, Bs + r * 64 + c * 16);
                    if (ks == 1 && nt2 == 3 && lane == 0)
                        mbar_arrive(sb + 64 + st * 8);   // all reads issued
#pragma unroll
                    for (int mt = 0; mt < 4; mt++) {
                        mma16816(acc[mt][nt2 * 2], a0[mt], q);
                        mma16816(acc[mt][nt2 * 2 + 1], a0[mt], q + 2);
                    }
                }
            }

            // distributed refill: rotating warp issues next stage's loads
            if ((gi & 7) == wid && lane == 0) {
                int f = gi + NST;
                if (f < GI) fill(f);
            }
        }

        // epilogue: registers -> gmem (+bias); stage smem untouched
        int m0 = mb * BM + m_warp;
        int n0 = nb * BN + n_warp;
        float2 bv[8];
#pragma unroll
        for (int nt = 0; nt < 8; nt++)
            bv[nt] = *reinterpret_cast<const float2*>(
                &bias[n0 + nt * 8 + (lane & 3) * 2]);
#pragma unroll
        for (int mt = 0; mt < 4; mt++) {
#pragma unroll
            for (int nt = 0; nt < 8; nt++) {
                int row = m0 + mt * 16 + (lane >> 2);
                int col = n0 + nt * 8 + (lane & 3) * 2;
                float2 v0 = make_float2(acc[mt][nt][0] + bv[nt].x,
                                        acc[mt][nt][1] + bv[nt].y);
                float2 v1 = make_float2(acc[mt][nt][2] + bv[nt].x,
                                        acc[mt][nt][3] + bv[nt].y);
                *reinterpret_cast<float2*>(&C[(size_t)row * N_DIM + col]) = v0;
                *reinterpret_cast<float2*>(&C[(size_t)(row + 8) * N_DIM + col]) = v1;
            }
        }
    }
}

// ---------------------------------------------------------------------------
// Launch
// ---------------------------------------------------------------------------
extern "C" void kernel_launch(void* const* d_in, const int* in_sizes, int n_in,
                              void* d_out, int out_size) {
    const float* A    = (const float*)d_in[0];
    const int*   B    = (const int*)  d_in[1];
    const float* s    = (const float*)d_in[2];
    const float* bias = (const float*)d_in[3];
    float* C = (float*)d_out;

    cudaFuncSetAttribute(gemm_hmma_kernel,
                         cudaFuncAttributeMaxDynamicSharedMemorySize, SMEM_BYTES);

    int nsm = 148;
    cudaDeviceGetAttribute(&nsm, cudaDevAttrMultiProcessorCount, 0);

    convA_kernel<<<(M_DIM * 512) / 256, 256>>>(A);
    dequant_kernel<<<((K_DIM / 16) * N_DIM) / 256, 256>>>(B, s);
    gemm_hmma_kernel<<<nsm, 256, SMEM_BYTES>>>(bias, C);
}

// round 11
// speedup vs baseline: 1.1816x; 1.0354x over previous
#include <cuda_runtime.h>
#include <cuda_fp16.h>
#include <cstdint>

#define M_DIM 4096
#define K_DIM 4096
#define N_DIM 12288

// GEMM tiling: R10 structure with BK=64 / NST=4
constexpr int BM = 128, BN = 256, BK = 64;
constexpr int KT = K_DIM / BK;                 // 64 k-tiles per output tile
constexpr int NTILES = (M_DIM / BM) * (N_DIM / BN);   // 1536
constexpr int NST = 4;                         // pipeline stages
constexpr int A_TILE = BM * BK * 2;            // 16384 B
constexpr int B_TILE = BN * BK * 2;            // 32768 B
constexpr int STAGE_BYTES = A_TILE + B_TILE;   // 49152
constexpr int SMEM_OFF = 1024;
constexpr int SMEM_BYTES = SMEM_OFF + NST * STAGE_BYTES;   // 197632

// tile-packed, pre-swizzled operand blobs (128B rows, chunk swz c ^ (r&7))
__device__ __half g_Apack[(size_t)M_DIM * K_DIM];   // tiles (mb*64+kt): 128x64
__device__ __half g_Bpack[(size_t)N_DIM * K_DIM];   // tiles (nb*64+kt): 256x64 [n][k]

// ---------------------------------------------------------------------------
// Pack A: fp32 [M,K] -> fp16 swizzled 128x64 tiles
// ---------------------------------------------------------------------------
__global__ void convA_kernel(const float* __restrict__ A) {
    int id = blockIdx.x * 256 + threadIdx.x;    // M*512 16B-chunk ids
    int m = id >> 9;
    int ch = id & 511;
    int kt = ch >> 3, c = ch & 7;
    const float4* src = reinterpret_cast<const float4*>(
        A + (size_t)m * K_DIM + kt * 64 + c * 8);
    float4 v0 = src[0], v1 = src[1];
    __half2 h[4];
    h[0] = __floats2half2_rn(v0.x, v0.y);
    h[1] = __floats2half2_rn(v0.z, v0.w);
    h[2] = __floats2half2_rn(v1.x, v1.y);
    h[3] = __floats2half2_rn(v1.z, v1.w);
    int mb = m >> 7, r = m & 127;
    int cs = c ^ (r & 7);
    char* dst = (char*)g_Apack + (size_t)(mb * 64 + kt) * A_TILE + r * 128 + cs * 16;
    *reinterpret_cast<uint4*>(dst) = *reinterpret_cast<uint4*>(h);
}

// ---------------------------------------------------------------------------
// Dequant+pack W: int4 -> fp16 swizzled 256x64 [n][k] tiles
// thread (t,o): k = t*16 + c8*8 + j, n = o
// ---------------------------------------------------------------------------
__global__ void dequant_kernel(const int* __restrict__ B, const float* __restrict__ s) {
    int id = blockIdx.x * 256 + threadIdx.x;    // (K/16)*N ids
    int t = id / N_DIM, o = id - t * N_DIM;
    int2 p = reinterpret_cast<const int2*>(B)[(size_t)t * N_DIM + o];
    float sc = s[(t >> 3) * N_DIM + o];
    __half2 h[8];
#pragma unroll
    for (int c8 = 0; c8 < 2; c8++) {
        int v = c8 ? p.y : p.x;
#pragma unroll
        for (int j = 0; j < 4; j++) {
            float w0 = (float)(((v >> (8 * j)) & 0xF) - 8) * sc;
            float w1 = (float)(((v >> (8 * j + 4)) & 0xF) - 8) * sc;
            h[c8 * 4 + j] = __floats2half2_rn(w0, w1);
        }
    }
    int kt = t >> 2;                 // 4 t-rows per 64-k tile
    int nb = o >> 8, r = o & 255;
    char* tile = (char*)g_Bpack + (size_t)(nb * 64 + kt) * B_TILE;
    int c0 = (t & 3) * 2;
    int xm = r & 7;
    *reinterpret_cast<uint4*>(tile + r * 128 + (c0 ^ xm) * 16)       = *reinterpret_cast<uint4*>(h);
    *reinterpret_cast<uint4*>(tile + r * 128 + ((c0 + 1) ^ xm) * 16) = *reinterpret_cast<uint4*>(h + 4);
}

// ---------------------------------------------------------------------------
// helpers
// ---------------------------------------------------------------------------
__device__ __forceinline__ uint32_t smem_u32(const void* p) {
    return (uint32_t)__cvta_generic_to_shared(p);
}
__device__ __forceinline__ void mbar_init(uint32_t a, uint32_t cnt) {
    asm volatile("mbarrier.init.shared.b64 [%0], %1;" :: "r"(a), "r"(cnt) : "memory");
}
__device__ __forceinline__ void mbar_expect_tx(uint32_t a, uint32_t bytes) {
    asm volatile("mbarrier.arrive.expect_tx.shared.b64 _, [%0], %1;"
                 :: "r"(a), "r"(bytes) : "memory");
}
__device__ __forceinline__ void mbar_arrive(uint32_t a) {
    asm volatile("mbarrier.arrive.shared.b64 _, [%0];" :: "r"(a) : "memory");
}
__device__ __forceinline__ void mbar_wait(uint32_t a, uint32_t parity) {
    asm volatile(
        "{\n\t.reg .pred P;\n"
        "W0_%=:\n\t"
        "mbarrier.try_wait.parity.acquire.cta.shared::cta.b64 P, [%0], %1, 0x989680;\n\t"
        "@P bra.uni W1_%=;\n\t"
        "bra.uni W0_%=;\n\t"
        "W1_%=:\n\t}"
        :: "r"(a), "r"(parity) : "memory");
}
__device__ __forceinline__ void bulk_g2s(uint32_t dst, const void* src,
                                         uint32_t bytes, uint32_t mbar) {
    asm volatile(
        "cp.async.bulk.shared::cluster.global.mbarrier::complete_tx::bytes "
        "[%0], [%1], %2, [%3];"
        :: "r"(dst), "l"(src), "r"(bytes), "r"(mbar) : "memory");
}
__device__ __forceinline__ void ldsm4(uint32_t* r, uint32_t addr) {
    asm volatile("ldmatrix.sync.aligned.m8n8.x4.shared.b16 {%0,%1,%2,%3}, [%4];"
                 : "=r"(r[0]), "=r"(r[1]), "=r"(r[2]), "=r"(r[3]) : "r"(addr));
}
__device__ __forceinline__ void mma16816(float* c, const uint32_t* a, const uint32_t* b) {
    asm volatile("mma.sync.aligned.m16n8k16.row.col.f32.f16.f16.f32 "
                 "{%0,%1,%2,%3}, {%4,%5,%6,%7}, {%8,%9}, {%0,%1,%2,%3};"
                 : "+f"(c[0]), "+f"(c[1]), "+f"(c[2]), "+f"(c[3])
                 : "r"(a[0]), "r"(a[1]), "r"(a[2]), "r"(a[3]),
                   "r"(b[0]), "r"(b[1]));
}

// ---------------------------------------------------------------------------
// Persistent GEMM. 256 threads = 8 compute warps (64x64). Distributed fill
// (rotating warp), fine-grain LDSM/MMA interleave, single-buffered frags.
// full[st]: tx barrier (1). empty[st]: 8 warp arrivals.
// ---------------------------------------------------------------------------
__global__ __launch_bounds__(256, 1)
void gemm_hmma_kernel(const float* __restrict__ bias, float* __restrict__ C) {
    extern __shared__ char smem[];
    uint32_t sb = smem_u32(smem);
    int tid = threadIdx.x, wid = tid >> 5, lane = tid & 31;
    int p = blockIdx.x, P = gridDim.x;

    if (tid == 0) {
#pragma unroll
        for (int st = 0; st < NST; st++) {
            mbar_init(sb + st * 8, 1);            // full[st]
            mbar_init(sb + 64 + st * 8, 8);       // empty[st]
        }
    }
    __syncthreads();

    int ntiles = (NTILES - p + P - 1) / P;
    int GI = ntiles * KT;

    // fill global iteration f's stage
    auto fill = [&](int f) {
        int st = f & (NST - 1);
        if (f >= NST) mbar_wait(sb + 64 + st * 8, ((f >> 2) - 1) & 1);
        int tile = p + (f >> 6) * P;
        int ktf = f & 63;
        int mbf = tile & 31, nbf = tile >> 5;
        uint32_t fb = sb + st * 8;
        mbar_expect_tx(fb, STAGE_BYTES);
        uint32_t sdst = sb + SMEM_OFF + st * STAGE_BYTES;
        bulk_g2s(sdst, (const char*)g_Apack + (size_t)(mbf * 64 + ktf) * A_TILE,
                 A_TILE, fb);
        bulk_g2s(sdst + A_TILE,
                 (const char*)g_Bpack + (size_t)(nbf * 64 + ktf) * B_TILE,
                 B_TILE, fb);
    };
    if (tid == 0) {
        for (int f = 0; f < NST && f < GI; f++) fill(f);
    }

    // per-thread ldmatrix geometry (warp tile 64x64, 128B smem rows)
    int g = lane >> 3, tr = lane & 7;
    int m_warp = (wid & 1) * 64;
    int n_warp = (wid >> 1) * 64;
    int aRow0 = m_warp + (g & 1) * 8 + tr;
    int aH = g >> 1;
    int bRow0 = n_warp + (g >> 1) * 8 + tr;
    int bH = g & 1;

    for (int tile_i = 0; tile_i < ntiles; tile_i++) {
        int tile = p + tile_i * P;
        int mb = tile & 31, nb = tile >> 5;

        float acc[4][8][4];
#pragma unroll
        for (int i = 0; i < 4; i++)
#pragma unroll
            for (int j = 0; j < 8; j++)
#pragma unroll
                for (int k = 0; k < 4; k++) acc[i][j][k] = 0.f;

        for (int kt = 0; kt < KT; kt++) {
            int gi = tile_i * KT + kt;
            int st = gi & (NST - 1);
            mbar_wait(sb + st * 8, (gi >> 2) & 1);
            uint32_t As = sb + SMEM_OFF + st * STAGE_BYTES;
            uint32_t Bs = As + A_TILE;

#pragma unroll
            for (int ks = 0; ks < 4; ks++) {
                int kc = 2 * ks;
                uint32_t a0[4][4];
#pragma unroll
                for (int mt = 0; mt < 4; mt++) {
                    int r = aRow0 + mt * 16;
                    int c = (kc + aH) ^ (r & 7);
                    ldsm4(a0[mt], As + r * 128 + c * 16);
                }
                // interleave: one B ldsm, then its 8 MMAs
#pragma unroll
                for (int nt2 = 0; nt2 < 4; nt2++) {
                    int r = bRow0 + nt2 * 16;
                    int c = (kc + bH) ^ (r & 7);
                    uint32_t q[4];
                    ldsm4(q, Bs + r * 128 + c * 16);
                    if (ks == 3 && nt2 == 3 && lane == 0)
                        mbar_arrive(sb + 64 + st * 8);   // all reads issued
#pragma unroll
                    for (int mt = 0; mt < 4; mt++) {
                        mma16816(acc[mt][nt2 * 2], a0[mt], q);
                        mma16816(acc[mt][nt2 * 2 + 1], a0[mt], q + 2);
                    }
                }
            }

            // distributed refill: rotating warp issues next stage's loads
            if ((gi & 7) == wid && lane == 0) {
                int f = gi + NST;
                if (f < GI) fill(f);
            }
        }

        // epilogue: registers -> gmem (+bias); stage smem untouched
        int m0 = mb * BM + m_warp;
        int n0 = nb * BN + n_warp;
        float2 bv[8];
#pragma unroll
        for (int nt = 0; nt < 8; nt++)
            bv[nt] = *reinterpret_cast<const float2*>(
                &bias[n0 + nt * 8 + (lane & 3) * 2]);
#pragma unroll
        for (int mt = 0; mt < 4; mt++) {
#pragma unroll
            for (int nt = 0; nt < 8; nt++) {
                int row = m0 + mt * 16 + (lane >> 2);
                int col = n0 + nt * 8 + (lane & 3) * 2;
                float2 v0 = make_float2(acc[mt][nt][0] + bv[nt].x,
                                        acc[mt][nt][1] + bv[nt].y);
                float2 v1 = make_float2(acc[mt][nt][2] + bv[nt].x,
                                        acc[mt][nt][3] + bv[nt].y);
                *reinterpret_cast<float2*>(&C[(size_t)row * N_DIM + col]) = v0;
                *reinterpret_cast<float2*>(&C[(size_t)(row + 8) * N_DIM + col]) = v1;
            }
        }
    }
}

// ---------------------------------------------------------------------------
// Launch
// ---------------------------------------------------------------------------
extern "C" void kernel_launch(void* const* d_in, const int* in_sizes, int n_in,
                              void* d_out, int out_size) {
    const float* A    = (const float*)d_in[0];
    const int*   B    = (const int*)  d_in[1];
    const float* s    = (const float*)d_in[2];
    const float* bias = (const float*)d_in[3];
    float* C = (float*)d_out;

    cudaFuncSetAttribute(gemm_hmma_kernel,
                         cudaFuncAttributeMaxDynamicSharedMemorySize, SMEM_BYTES);

    int nsm = 148;
    cudaDeviceGetAttribute(&nsm, cudaDevAttrMultiProcessorCount, 0);

    convA_kernel<<<(M_DIM * 512) / 256, 256>>>(A);
    dequant_kernel<<<((K_DIM / 16) * N_DIM) / 256, 256>>>(B, s);
    gemm_hmma_kernel<<<nsm, 256, SMEM_BYTES>>>(bias, C);
}

// round 12
// speedup vs baseline: 1.1850x; 1.0028x over previous
#include <cuda_runtime.h>
#include <cuda_fp16.h>
#include <cstdint>

#define M_DIM 4096
#define K_DIM 4096
#define N_DIM 12288

// GEMM tiling: R10 structure with BK=64 / NST=4
constexpr int BM = 128, BN = 256, BK = 64;
constexpr int KT = K_DIM / BK;                 // 64 k-tiles per output tile
constexpr int NTILES = (M_DIM / BM) * (N_DIM / BN);   // 1536
constexpr int NST = 4;                         // pipeline stages
constexpr int A_TILE = BM * BK * 2;            // 16384 B
constexpr int B_TILE = BN * BK * 2;            // 32768 B
constexpr int STAGE_BYTES = A_TILE + B_TILE;   // 49152
constexpr int SMEM_OFF = 1024;
constexpr int SMEM_BYTES = SMEM_OFF + NST * STAGE_BYTES;   // 197632

// tile-packed, pre-swizzled operand blobs (128B rows, chunk swz c ^ (r&7))
__device__ __half g_Apack[(size_t)M_DIM * K_DIM];   // tiles (mb*64+kt): 128x64
__device__ __half g_Bpack[(size_t)N_DIM * K_DIM];   // tiles (nb*64+kt): 256x64 [n][k]

// ---------------------------------------------------------------------------
// Pack A: fp32 [M,K] -> fp16 swizzled 128x64 tiles
// ---------------------------------------------------------------------------
__global__ void convA_kernel(const float* __restrict__ A) {
    int id = blockIdx.x * 256 + threadIdx.x;    // M*512 16B-chunk ids
    int m = id >> 9;
    int ch = id & 511;
    int kt = ch >> 3, c = ch & 7;
    const float4* src = reinterpret_cast<const float4*>(
        A + (size_t)m * K_DIM + kt * 64 + c * 8);
    float4 v0 = src[0], v1 = src[1];
    __half2 h[4];
    h[0] = __floats2half2_rn(v0.x, v0.y);
    h[1] = __floats2half2_rn(v0.z, v0.w);
    h[2] = __floats2half2_rn(v1.x, v1.y);
    h[3] = __floats2half2_rn(v1.z, v1.w);
    int mb = m >> 7, r = m & 127;
    int cs = c ^ (r & 7);
    char* dst = (char*)g_Apack + (size_t)(mb * 64 + kt) * A_TILE + r * 128 + cs * 16;
    *reinterpret_cast<uint4*>(dst) = *reinterpret_cast<uint4*>(h);
}

// ---------------------------------------------------------------------------
// Dequant+pack W: int4 -> fp16 swizzled 256x64 [n][k] tiles
// thread (t,o): k = t*16 + c8*8 + j, n = o
// ---------------------------------------------------------------------------
__global__ void dequant_kernel(const int* __restrict__ B, const float* __restrict__ s) {
    int id = blockIdx.x * 256 + threadIdx.x;    // (K/16)*N ids
    int t = id / N_DIM, o = id - t * N_DIM;
    int2 p = reinterpret_cast<const int2*>(B)[(size_t)t * N_DIM + o];
    float sc = s[(t >> 3) * N_DIM + o];
    __half2 h[8];
#pragma unroll
    for (int c8 = 0; c8 < 2; c8++) {
        int v = c8 ? p.y : p.x;
#pragma unroll
        for (int j = 0; j < 4; j++) {
            float w0 = (float)(((v >> (8 * j)) & 0xF) - 8) * sc;
            float w1 = (float)(((v >> (8 * j + 4)) & 0xF) - 8) * sc;
            h[c8 * 4 + j] = __floats2half2_rn(w0, w1);
        }
    }
    int kt = t >> 2;                 // 4 t-rows per 64-k tile
    int nb = o >> 8, r = o & 255;
    char* tile = (char*)g_Bpack + (size_t)(nb * 64 + kt) * B_TILE;
    int c0 = (t & 3) * 2;
    int xm = r & 7;
    *reinterpret_cast<uint4*>(tile + r * 128 + (c0 ^ xm) * 16)       = *reinterpret_cast<uint4*>(h);
    *reinterpret_cast<uint4*>(tile + r * 128 + ((c0 + 1) ^ xm) * 16) = *reinterpret_cast<uint4*>(h + 4);
}

// ---------------------------------------------------------------------------
// helpers
// ---------------------------------------------------------------------------
__device__ __forceinline__ uint32_t smem_u32(const void* p) {
    return (uint32_t)__cvta_generic_to_shared(p);
}
__device__ __forceinline__ void mbar_init(uint32_t a, uint32_t cnt) {
    asm volatile("mbarrier.init.shared.b64 [%0], %1;" :: "r"(a), "r"(cnt) : "memory");
}
__device__ __forceinline__ void mbar_expect_tx(uint32_t a, uint32_t bytes) {
    asm volatile("mbarrier.arrive.expect_tx.shared.b64 _, [%0], %1;"
                 :: "r"(a), "r"(bytes) : "memory");
}
__device__ __forceinline__ void mbar_arrive(uint32_t a) {
    asm volatile("mbarrier.arrive.shared.b64 _, [%0];" :: "r"(a) : "memory");
}
__device__ __forceinline__ void mbar_wait(uint32_t a, uint32_t parity) {
    asm volatile(
        "{\n\t.reg .pred P;\n"
        "W0_%=:\n\t"
        "mbarrier.try_wait.parity.acquire.cta.shared::cta.b64 P, [%0], %1, 0x989680;\n\t"
        "@P bra.uni W1_%=;\n\t"
        "bra.uni W0_%=;\n\t"
        "W1_%=:\n\t}"
        :: "r"(a), "r"(parity) : "memory");
}
__device__ __forceinline__ void bulk_g2s(uint32_t dst, const void* src,
                                         uint32_t bytes, uint32_t mbar) {
    asm volatile(
        "cp.async.bulk.shared::cluster.global.mbarrier::complete_tx::bytes "
        "[%0], [%1], %2, [%3];"
        :: "r"(dst), "l"(src), "r"(bytes), "r"(mbar) : "memory");
}
__device__ __forceinline__ void ldsm4(uint32_t* r, uint32_t addr) {
    asm volatile("ldmatrix.sync.aligned.m8n8.x4.shared.b16 {%0,%1,%2,%3}, [%4];"
                 : "=r"(r[0]), "=r"(r[1]), "=r"(r[2]), "=r"(r[3]) : "r"(addr));
}
__device__ __forceinline__ void mma16816(float* c, const uint32_t* a, const uint32_t* b) {
    asm volatile("mma.sync.aligned.m16n8k16.row.col.f32.f16.f16.f32 "
                 "{%0,%1,%2,%3}, {%4,%5,%6,%7}, {%8,%9}, {%0,%1,%2,%3};"
                 : "+f"(c[0]), "+f"(c[1]), "+f"(c[2]), "+f"(c[3])
                 : "r"(a[0]), "r"(a[1]), "r"(a[2]), "r"(a[3]),
                   "r"(b[0]), "r"(b[1]));
}

// ---------------------------------------------------------------------------
// Persistent GEMM. 256 threads = 8 compute warps (64x64). Distributed fill
// (rotating warp), fine-grain LDSM/MMA interleave, single-buffered frags.
// full[st]: tx barrier (1). empty[st]: 8 warp arrivals.
// ---------------------------------------------------------------------------
__global__ __launch_bounds__(256, 1)
void gemm_hmma_kernel(const float* __restrict__ bias, float* __restrict__ C) {
    extern __shared__ char smem[];
    uint32_t sb = smem_u32(smem);
    int tid = threadIdx.x, wid = tid >> 5, lane = tid & 31;
    int p = blockIdx.x, P = gridDim.x;

    if (tid == 0) {
#pragma unroll
        for (int st = 0; st < NST; st++) {
            mbar_init(sb + st * 8, 1);            // full[st]
            mbar_init(sb + 64 + st * 8, 8);       // empty[st]
        }
    }
    __syncthreads();

    int ntiles = (NTILES - p + P - 1) / P;
    int GI = ntiles * KT;

    // fill global iteration f's stage
    auto fill = [&](int f) {
        int st = f & (NST - 1);
        if (f >= NST) mbar_wait(sb + 64 + st * 8, ((f >> 2) - 1) & 1);
        int tile = p + (f >> 6) * P;
        int ktf = f & 63;
        int mbf = tile & 31, nbf = tile >> 5;
        uint32_t fb = sb + st * 8;
        mbar_expect_tx(fb, STAGE_BYTES);
        uint32_t sdst = sb + SMEM_OFF + st * STAGE_BYTES;
        bulk_g2s(sdst, (const char*)g_Apack + (size_t)(mbf * 64 + ktf) * A_TILE,
                 A_TILE, fb);
        bulk_g2s(sdst + A_TILE,
                 (const char*)g_Bpack + (size_t)(nbf * 64 + ktf) * B_TILE,
                 B_TILE, fb);
    };
    if (tid == 0) {
        for (int f = 0; f < NST && f < GI; f++) fill(f);
    }

    // per-thread ldmatrix geometry (warp tile 64x64, 128B smem rows)
    int g = lane >> 3, tr = lane & 7;
    int m_warp = (wid & 1) * 64;
    int n_warp = (wid >> 1) * 64;
    int aRow0 = m_warp + (g & 1) * 8 + tr;
    int aH = g >> 1;
    int bRow0 = n_warp + (g >> 1) * 8 + tr;
    int bH = g & 1;

    for (int tile_i = 0; tile_i < ntiles; tile_i++) {
        int tile = p + tile_i * P;
        int mb = tile & 31, nb = tile >> 5;

        float acc[4][8][4];
#pragma unroll
        for (int i = 0; i < 4; i++)
#pragma unroll
            for (int j = 0; j < 8; j++)
#pragma unroll
                for (int k = 0; k < 4; k++) acc[i][j][k] = 0.f;

        for (int kt = 0; kt < KT; kt++) {
            int gi = tile_i * KT + kt;
            int st = gi & (NST - 1);
            mbar_wait(sb + st * 8, (gi >> 2) & 1);
            uint32_t As = sb + SMEM_OFF + st * STAGE_BYTES;
            uint32_t Bs = As + A_TILE;

#pragma unroll
            for (int ks = 0; ks < 4; ks++) {
                int kc = 2 * ks;
                uint32_t a0[4][4];
#pragma unroll
                for (int mt = 0; mt < 4; mt++) {
                    int r = aRow0 + mt * 16;
                    int c = (kc + aH) ^ (r & 7);
                    ldsm4(a0[mt], As + r * 128 + c * 16);
                }
                // interleave: one B ldsm, then its 8 MMAs
#pragma unroll
                for (int nt2 = 0; nt2 < 4; nt2++) {
                    int r = bRow0 + nt2 * 16;
                    int c = (kc + bH) ^ (r & 7);
                    uint32_t q[4];
                    ldsm4(q, Bs + r * 128 + c * 16);
                    if (ks == 3 && nt2 == 3 && lane == 0)
                        mbar_arrive(sb + 64 + st * 8);   // all reads issued
#pragma unroll
                    for (int mt = 0; mt < 4; mt++) {
                        mma16816(acc[mt][nt2 * 2], a0[mt], q);
                        mma16816(acc[mt][nt2 * 2 + 1], a0[mt], q + 2);
                    }
                }
            }

            // distributed refill: rotating warp issues next stage's loads
            if ((gi & 7) == wid && lane == 0) {
                int f = gi + NST;
                if (f < GI) fill(f);
            }
        }

        // epilogue: registers -> gmem (+bias); stage smem untouched
        int m0 = mb * BM + m_warp;
        int n0 = nb * BN + n_warp;
        float2 bv[8];
#pragma unroll
        for (int nt = 0; nt < 8; nt++)
            bv[nt] = *reinterpret_cast<const float2*>(
                &bias[n0 + nt * 8 + (lane & 3) * 2]);
#pragma unroll
        for (int mt = 0; mt < 4; mt++) {
#pragma unroll
            for (int nt = 0; nt < 8; nt++) {
                int row = m0 + mt * 16 + (lane >> 2);
                int col = n0 + nt * 8 + (lane & 3) * 2;
                float2 v0 = make_float2(acc[mt][nt][0] + bv[nt].x,
                                        acc[mt][nt][1] + bv[nt].y);
                float2 v1 = make_float2(acc[mt][nt][2] + bv[nt].x,
                                        acc[mt][nt][3] + bv[nt].y);
                *reinterpret_cast<float2*>(&C[(size_t)row * N_DIM + col]) = v0;
                *reinterpret_cast<float2*>(&C[(size_t)(row + 8) * N_DIM + col]) = v1;
            }
        }
    }
}

// ---------------------------------------------------------------------------
// Launch
// ---------------------------------------------------------------------------
extern "C" void kernel_launch(void* const* d_in, const int* in_sizes, int n_in,
                              void* d_out, int out_size) {
    const float* A    = (const float*)d_in[0];
    const int*   B    = (const int*)  d_in[1];
    const float* s    = (const float*)d_in[2];
    const float* bias = (const float*)d_in[3];
    float* C = (float*)d_out;

    cudaFuncSetAttribute(gemm_hmma_kernel,
                         cudaFuncAttributeMaxDynamicSharedMemorySize, SMEM_BYTES);

    int nsm = 148;
    cudaDeviceGetAttribute(&nsm, cudaDevAttrMultiProcessorCount, 0);

    convA_kernel<<<(M_DIM * 512) / 256, 256>>>(A);
    dequant_kernel<<<((K_DIM / 16) * N_DIM) / 256, 256>>>(B, s);
    gemm_hmma_kernel<<<nsm, 256, SMEM_BYTES>>>(bias, C);
}

// round 13
// speedup vs baseline: 1.2101x; 1.0212x over previous
#include <cuda_runtime.h>
#include <cuda_fp16.h>
#include <cstdint>

#define M_DIM 4096
#define K_DIM 4096
#define N_DIM 12288

// GEMM tiling: BN=192 for wave balance (2048 tiles, max 14/CTA vs avg 13.84)
constexpr int BM = 128, BN = 192, BK = 64;
constexpr int KT = K_DIM / BK;                 // 64 k-tiles per output tile
constexpr int NTILES = (M_DIM / BM) * (N_DIM / BN);   // 32 * 64 = 2048
constexpr int NST = 4;                         // pipeline stages
constexpr int A_TILE = BM * BK * 2;            // 16384 B
constexpr int B_TILE = BN * BK * 2;            // 24576 B
constexpr int STAGE_BYTES = A_TILE + B_TILE;   // 40960
constexpr int SMEM_OFF = 1024;
constexpr int SMEM_BYTES = SMEM_OFF + NST * STAGE_BYTES;   // 164864

// tile-packed, pre-swizzled operand blobs (128B rows, chunk swz c ^ (r&7))
__device__ __half g_Apack[(size_t)M_DIM * K_DIM];   // tiles (mb*64+kt): 128x64
__device__ __half g_Bpack[(size_t)N_DIM * K_DIM];   // tiles (nb*64+kt): 192x64 [n][k]

// ---------------------------------------------------------------------------
// Pack A: fp32 [M,K] -> fp16 swizzled 128x64 tiles
// ---------------------------------------------------------------------------
__global__ void convA_kernel(const float* __restrict__ A) {
    int id = blockIdx.x * 256 + threadIdx.x;    // M*512 16B-chunk ids
    int m = id >> 9;
    int ch = id & 511;
    int kt = ch >> 3, c = ch & 7;
    const float4* src = reinterpret_cast<const float4*>(
        A + (size_t)m * K_DIM + kt * 64 + c * 8);
    float4 v0 = src[0], v1 = src[1];
    __half2 h[4];
    h[0] = __floats2half2_rn(v0.x, v0.y);
    h[1] = __floats2half2_rn(v0.z, v0.w);
    h[2] = __floats2half2_rn(v1.x, v1.y);
    h[3] = __floats2half2_rn(v1.z, v1.w);
    int mb = m >> 7, r = m & 127;
    int cs = c ^ (r & 7);
    char* dst = (char*)g_Apack + (size_t)(mb * 64 + kt) * A_TILE + r * 128 + cs * 16;
    *reinterpret_cast<uint4*>(dst) = *reinterpret_cast<uint4*>(h);
}

// ---------------------------------------------------------------------------
// Dequant+pack W: int4 -> fp16 swizzled 192x64 [n][k] tiles
// thread (t,o): k = t*16 + c8*8 + j, n = o
// ---------------------------------------------------------------------------
__global__ void dequant_kernel(const int* __restrict__ B, const float* __restrict__ s) {
    int id = blockIdx.x * 256 + threadIdx.x;    // (K/16)*N ids
    int t = id / N_DIM, o = id - t * N_DIM;
    int2 p = reinterpret_cast<const int2*>(B)[(size_t)t * N_DIM + o];
    float sc = s[(t >> 3) * N_DIM + o];
    __half2 h[8];
#pragma unroll
    for (int c8 = 0; c8 < 2; c8++) {
        int v = c8 ? p.y : p.x;
#pragma unroll
        for (int j = 0; j < 4; j++) {
            float w0 = (float)(((v >> (8 * j)) & 0xF) - 8) * sc;
            float w1 = (float)(((v >> (8 * j + 4)) & 0xF) - 8) * sc;
            h[c8 * 4 + j] = __floats2half2_rn(w0, w1);
        }
    }
    int kt = t >> 2;                 // 4 t-rows per 64-k tile
    int nb = o / BN, r = o - nb * BN;
    char* tile = (char*)g_Bpack + (size_t)(nb * 64 + kt) * B_TILE;
    int c0 = (t & 3) * 2;
    int xm = r & 7;
    *reinterpret_cast<uint4*>(tile + r * 128 + (c0 ^ xm) * 16)       = *reinterpret_cast<uint4*>(h);
    *reinterpret_cast<uint4*>(tile + r * 128 + ((c0 + 1) ^ xm) * 16) = *reinterpret_cast<uint4*>(h + 4);
}

// ---------------------------------------------------------------------------
// helpers
// ---------------------------------------------------------------------------
__device__ __forceinline__ uint32_t smem_u32(const void* p) {
    return (uint32_t)__cvta_generic_to_shared(p);
}
__device__ __forceinline__ void mbar_init(uint32_t a, uint32_t cnt) {
    asm volatile("mbarrier.init.shared.b64 [%0], %1;" :: "r"(a), "r"(cnt) : "memory");
}
__device__ __forceinline__ void mbar_expect_tx(uint32_t a, uint32_t bytes) {
    asm volatile("mbarrier.arrive.expect_tx.shared.b64 _, [%0], %1;"
                 :: "r"(a), "r"(bytes) : "memory");
}
__device__ __forceinline__ void mbar_arrive(uint32_t a) {
    asm volatile("mbarrier.arrive.shared.b64 _, [%0];" :: "r"(a) : "memory");
}
__device__ __forceinline__ void mbar_wait(uint32_t a, uint32_t parity) {
    asm volatile(
        "{\n\t.reg .pred P;\n"
        "W0_%=:\n\t"
        "mbarrier.try_wait.parity.acquire.cta.shared::cta.b64 P, [%0], %1, 0x989680;\n\t"
        "@P bra.uni W1_%=;\n\t"
        "bra.uni W0_%=;\n\t"
        "W1_%=:\n\t}"
        :: "r"(a), "r"(parity) : "memory");
}
__device__ __forceinline__ void bulk_g2s(uint32_t dst, const void* src,
                                         uint32_t bytes, uint32_t mbar) {
    asm volatile(
        "cp.async.bulk.shared::cluster.global.mbarrier::complete_tx::bytes "
        "[%0], [%1], %2, [%3];"
        :: "r"(dst), "l"(src), "r"(bytes), "r"(mbar) : "memory");
}
__device__ __forceinline__ void ldsm4(uint32_t* r, uint32_t addr) {
    asm volatile("ldmatrix.sync.aligned.m8n8.x4.shared.b16 {%0,%1,%2,%3}, [%4];"
                 : "=r"(r[0]), "=r"(r[1]), "=r"(r[2]), "=r"(r[3]) : "r"(addr));
}
__device__ __forceinline__ void mma16816(float* c, const uint32_t* a, const uint32_t* b) {
    asm volatile("mma.sync.aligned.m16n8k16.row.col.f32.f16.f16.f32 "
                 "{%0,%1,%2,%3}, {%4,%5,%6,%7}, {%8,%9}, {%0,%1,%2,%3};"
                 : "+f"(c[0]), "+f"(c[1]), "+f"(c[2]), "+f"(c[3])
                 : "r"(a[0]), "r"(a[1]), "r"(a[2]), "r"(a[3]),
                   "r"(b[0]), "r"(b[1]));
}

// ---------------------------------------------------------------------------
// Persistent GEMM. 256 threads = 8 compute warps (64x48). Distributed fill
// (rotating warp), fine-grain LDSM/MMA interleave, single-buffered frags.
// full[st]: tx barrier (1). empty[st]: 8 warp arrivals.
// ---------------------------------------------------------------------------
__global__ __launch_bounds__(256, 1)
void gemm_hmma_kernel(const float* __restrict__ bias, float* __restrict__ C) {
    extern __shared__ char smem[];
    uint32_t sb = smem_u32(smem);
    int tid = threadIdx.x, wid = tid >> 5, lane = tid & 31;
    int p = blockIdx.x, P = gridDim.x;

    if (tid == 0) {
#pragma unroll
        for (int st = 0; st < NST; st++) {
            mbar_init(sb + st * 8, 1);            // full[st]
            mbar_init(sb + 64 + st * 8, 8);       // empty[st]
        }
    }
    __syncthreads();

    int ntiles = (NTILES - p + P - 1) / P;
    int GI = ntiles * KT;

    // fill global iteration f's stage
    auto fill = [&](int f) {
        int st = f & (NST - 1);
        if (f >= NST) mbar_wait(sb + 64 + st * 8, ((f >> 2) - 1) & 1);
        int tile = p + (f >> 6) * P;
        int ktf = f & 63;
        int mbf = tile & 31, nbf = tile >> 5;
        uint32_t fb = sb + st * 8;
        mbar_expect_tx(fb, STAGE_BYTES);
        uint32_t sdst = sb + SMEM_OFF + st * STAGE_BYTES;
        bulk_g2s(sdst, (const char*)g_Apack + (size_t)(mbf * 64 + ktf) * A_TILE,
                 A_TILE, fb);
        bulk_g2s(sdst + A_TILE,
                 (const char*)g_Bpack + (size_t)(nbf * 64 + ktf) * B_TILE,
                 B_TILE, fb);
    };
    if (tid == 0) {
        for (int f = 0; f < NST && f < GI; f++) fill(f);
    }

    // per-thread ldmatrix geometry (warp tile 64x48, 128B smem rows)
    int g = lane >> 3, tr = lane & 7;
    int m_warp = (wid & 1) * 64;
    int n_warp = (wid >> 1) * 48;
    int aRow0 = m_warp + (g & 1) * 8 + tr;
    int aH = g >> 1;
    int bRow0 = n_warp + (g >> 1) * 8 + tr;
    int bH = g & 1;

    for (int tile_i = 0; tile_i < ntiles; tile_i++) {
        int tile = p + tile_i * P;
        int mb = tile & 31, nb = tile >> 5;

        float acc[4][6][4];
#pragma unroll
        for (int i = 0; i < 4; i++)
#pragma unroll
            for (int j = 0; j < 6; j++)
#pragma unroll
                for (int k = 0; k < 4; k++) acc[i][j][k] = 0.f;

        for (int kt = 0; kt < KT; kt++) {
            int gi = tile_i * KT + kt;
            int st = gi & (NST - 1);
            mbar_wait(sb + st * 8, (gi >> 2) & 1);
            uint32_t As = sb + SMEM_OFF + st * STAGE_BYTES;
            uint32_t Bs = As + A_TILE;

#pragma unroll
            for (int ks = 0; ks < 4; ks++) {
                int kc = 2 * ks;
                uint32_t a0[4][4];
#pragma unroll
                for (int mt = 0; mt < 4; mt++) {
                    int r = aRow0 + mt * 16;
                    int c = (kc + aH) ^ (r & 7);
                    ldsm4(a0[mt], As + r * 128 + c * 16);
                }
                // interleave: one B ldsm, then its 8 MMAs
#pragma unroll
                for (int nt2 = 0; nt2 < 3; nt2++) {
                    int r = bRow0 + nt2 * 16;
                    int c = (kc + bH) ^ (r & 7);
                    uint32_t q[4];
                    ldsm4(q, Bs + r * 128 + c * 16);
                    if (ks == 3 && nt2 == 2 && lane == 0)
                        mbar_arrive(sb + 64 + st * 8);   // all reads issued
#pragma unroll
                    for (int mt = 0; mt < 4; mt++) {
                        mma16816(acc[mt][nt2 * 2], a0[mt], q);
                        mma16816(acc[mt][nt2 * 2 + 1], a0[mt], q + 2);
                    }
                }
            }

            // distributed refill: rotating warp issues next stage's loads
            if ((gi & 7) == wid && lane == 0) {
                int f = gi + NST;
                if (f < GI) fill(f);
            }
        }

        // epilogue: registers -> gmem (+bias); stage smem untouched
        int m0 = mb * BM + m_warp;
        int n0 = nb * BN + n_warp;
        float2 bv[6];
#pragma unroll
        for (int nt = 0; nt < 6; nt++)
            bv[nt] = *reinterpret_cast<const float2*>(
                &bias[n0 + nt * 8 + (lane & 3) * 2]);
#pragma unroll
        for (int mt = 0; mt < 4; mt++) {
#pragma unroll
            for (int nt = 0; nt < 6; nt++) {
                int row = m0 + mt * 16 + (lane >> 2);
                int col = n0 + nt * 8 + (lane & 3) * 2;
                float2 v0 = make_float2(acc[mt][nt][0] + bv[nt].x,
                                        acc[mt][nt][1] + bv[nt].y);
                float2 v1 = make_float2(acc[mt][nt][2] + bv[nt].x,
                                        acc[mt][nt][3] + bv[nt].y);
                *reinterpret_cast<float2*>(&C[(size_t)row * N_DIM + col]) = v0;
                *reinterpret_cast<float2*>(&C[(size_t)(row + 8) * N_DIM + col]) = v1;
            }
        }
    }
}

// ---------------------------------------------------------------------------
// Launch
// ---------------------------------------------------------------------------
extern "C" void kernel_launch(void* const* d_in, const int* in_sizes, int n_in,
                              void* d_out, int out_size) {
    const float* A    = (const float*)d_in[0];
    const int*   B    = (const int*)  d_in[1];
    const float* s    = (const float*)d_in[2];
    const float* bias = (const float*)d_in[3];
    float* C = (float*)d_out;

    cudaFuncSetAttribute(gemm_hmma_kernel,
                         cudaFuncAttributeMaxDynamicSharedMemorySize, SMEM_BYTES);

    int nsm = 148;
    cudaDeviceGetAttribute(&nsm, cudaDevAttrMultiProcessorCount, 0);

    convA_kernel<<<(M_DIM * 512) / 256, 256>>>(A);
    dequant_kernel<<<((K_DIM / 16) * N_DIM) / 256, 256>>>(B, s);
    gemm_hmma_kernel<<<nsm, 256, SMEM_BYTES>>>(bias, C);
}

// round 14
// speedup vs baseline: 1.2352x; 1.0207x over previous
#include <cuda_runtime.h>
#include <cuda_fp16.h>
#include <cstdint>

#define M_DIM 4096
#define K_DIM 4096
#define N_DIM 12288

// GEMM tiling: BN=192 for wave balance (2048 tiles, max 14/CTA vs avg 13.84)
constexpr int BM = 128, BN = 192, BK = 64;
constexpr int KT = K_DIM / BK;                 // 64 k-tiles per output tile
constexpr int NTILES = (M_DIM / BM) * (N_DIM / BN);   // 32 * 64 = 2048
constexpr int NST = 4;                         // pipeline stages
constexpr int A_TILE = BM * BK * 2;            // 16384 B
constexpr int B_TILE = BN * BK * 2;            // 24576 B
constexpr int STAGE_BYTES = A_TILE + B_TILE;   // 40960
constexpr int SMEM_OFF = 1024;
constexpr int SMEM_BYTES = SMEM_OFF + NST * STAGE_BYTES;   // 164864

// tile-packed, pre-swizzled operand blobs (128B rows, chunk swz c ^ (r&7))
__device__ __half g_Apack[(size_t)M_DIM * K_DIM];   // tiles (mb*64+kt): 128x64
__device__ __half g_Bpack[(size_t)N_DIM * K_DIM];   // tiles (nb*64+kt): 192x64 [n][k]

// ---------------------------------------------------------------------------
// Pack A: fp32 [M,K] -> fp16 swizzled 128x64 tiles
// ---------------------------------------------------------------------------
__global__ void convA_kernel(const float* __restrict__ A) {
    int id = blockIdx.x * 256 + threadIdx.x;    // M*512 16B-chunk ids
    int m = id >> 9;
    int ch = id & 511;
    int kt = ch >> 3, c = ch & 7;
    const float4* src = reinterpret_cast<const float4*>(
        A + (size_t)m * K_DIM + kt * 64 + c * 8);
    float4 v0 = src[0], v1 = src[1];
    __half2 h[4];
    h[0] = __floats2half2_rn(v0.x, v0.y);
    h[1] = __floats2half2_rn(v0.z, v0.w);
    h[2] = __floats2half2_rn(v1.x, v1.y);
    h[3] = __floats2half2_rn(v1.z, v1.w);
    int mb = m >> 7, r = m & 127;
    int cs = c ^ (r & 7);
    char* dst = (char*)g_Apack + (size_t)(mb * 64 + kt) * A_TILE + r * 128 + cs * 16;
    *reinterpret_cast<uint4*>(dst) = *reinterpret_cast<uint4*>(h);
}

// ---------------------------------------------------------------------------
// Dequant+pack W (smem-staged, coalesced): one block per (nb, kt) tile.
// Thread o_l dequants the full 64-k row of n = nb*192+o_l into a swizzled
// smem tile; block then streams the tile to gmem with linear 16B stores.
// Byte-identical output to the unstaged version.
// ---------------------------------------------------------------------------
__global__ __launch_bounds__(192, 4)
void dequant_kernel(const int* __restrict__ B, const float* __restrict__ s) {
    __shared__ char tile_s[B_TILE];
    int nb = blockIdx.x;            // 0..63
    int kt = blockIdx.y;            // 0..63
    int o_l = threadIdx.x;          // 0..191
    int o = nb * BN + o_l;
    int xm = o_l & 7;
#pragma unroll
    for (int tt = 0; tt < 4; tt++) {
        int t = kt * 4 + tt;
        int2 p = reinterpret_cast<const int2*>(B)[(size_t)t * N_DIM + o];
        float sc = s[(t >> 3) * N_DIM + o];
        __half2 h[8];
#pragma unroll
        for (int c8 = 0; c8 < 2; c8++) {
            int v = c8 ? p.y : p.x;
#pragma unroll
            for (int j = 0; j < 4; j++) {
                float w0 = (float)(((v >> (8 * j)) & 0xF) - 8) * sc;
                float w1 = (float)(((v >> (8 * j + 4)) & 0xF) - 8) * sc;
                h[c8 * 4 + j] = __floats2half2_rn(w0, w1);
            }
        }
        int c0 = tt * 2;
        *reinterpret_cast<uint4*>(tile_s + o_l * 128 + ((c0 ^ xm) * 16)) =
            *reinterpret_cast<uint4*>(h);
        *reinterpret_cast<uint4*>(tile_s + o_l * 128 + (((c0 + 1) ^ xm) * 16)) =
            *reinterpret_cast<uint4*>(h + 4);
    }
    __syncthreads();
    uint4* dst = reinterpret_cast<uint4*>(
        (char*)g_Bpack + (size_t)(nb * 64 + kt) * B_TILE);
    const uint4* srcp = reinterpret_cast<const uint4*>(tile_s);
#pragma unroll
    for (int i = 0; i < B_TILE / 16 / 192; i++)
        dst[i * 192 + threadIdx.x] = srcp[i * 192 + threadIdx.x];
}

// ---------------------------------------------------------------------------
// helpers
// ---------------------------------------------------------------------------
__device__ __forceinline__ uint32_t smem_u32(const void* p) {
    return (uint32_t)__cvta_generic_to_shared(p);
}
__device__ __forceinline__ void mbar_init(uint32_t a, uint32_t cnt) {
    asm volatile("mbarrier.init.shared.b64 [%0], %1;" :: "r"(a), "r"(cnt) : "memory");
}
__device__ __forceinline__ void mbar_expect_tx(uint32_t a, uint32_t bytes) {
    asm volatile("mbarrier.arrive.expect_tx.shared.b64 _, [%0], %1;"
                 :: "r"(a), "r"(bytes) : "memory");
}
__device__ __forceinline__ void mbar_arrive(uint32_t a) {
    asm volatile("mbarrier.arrive.shared.b64 _, [%0];" :: "r"(a) : "memory");
}
__device__ __forceinline__ void mbar_wait(uint32_t a, uint32_t parity) {
    asm volatile(
        "{\n\t.reg .pred P;\n"
        "W0_%=:\n\t"
        "mbarrier.try_wait.parity.acquire.cta.shared::cta.b64 P, [%0], %1, 0x989680;\n\t"
        "@P bra.uni W1_%=;\n\t"
        "bra.uni W0_%=;\n\t"
        "W1_%=:\n\t}"
        :: "r"(a), "r"(parity) : "memory");
}
__device__ __forceinline__ void bulk_g2s(uint32_t dst, const void* src,
                                         uint32_t bytes, uint32_t mbar) {
    asm volatile(
        "cp.async.bulk.shared::cluster.global.mbarrier::complete_tx::bytes "
        "[%0], [%1], %2, [%3];"
        :: "r"(dst), "l"(src), "r"(bytes), "r"(mbar) : "memory");
}
__device__ __forceinline__ void ldsm4(uint32_t* r, uint32_t addr) {
    asm volatile("ldmatrix.sync.aligned.m8n8.x4.shared.b16 {%0,%1,%2,%3}, [%4];"
                 : "=r"(r[0]), "=r"(r[1]), "=r"(r[2]), "=r"(r[3]) : "r"(addr));
}
__device__ __forceinline__ void mma16816(float* c, const uint32_t* a, const uint32_t* b) {
    asm volatile("mma.sync.aligned.m16n8k16.row.col.f32.f16.f16.f32 "
                 "{%0,%1,%2,%3}, {%4,%5,%6,%7}, {%8,%9}, {%0,%1,%2,%3};"
                 : "+f"(c[0]), "+f"(c[1]), "+f"(c[2]), "+f"(c[3])
                 : "r"(a[0]), "r"(a[1]), "r"(a[2]), "r"(a[3]),
                   "r"(b[0]), "r"(b[1]));
}

// ---------------------------------------------------------------------------
// Persistent GEMM. 256 threads = 8 compute warps (64x48). Distributed fill
// (rotating warp), fine-grain LDSM/MMA interleave, single-buffered frags.
// full[st]: tx barrier (1). empty[st]: 8 warp arrivals.
// ---------------------------------------------------------------------------
__global__ __launch_bounds__(256, 1)
void gemm_hmma_kernel(const float* __restrict__ bias, float* __restrict__ C) {
    extern __shared__ char smem[];
    uint32_t sb = smem_u32(smem);
    int tid = threadIdx.x, wid = tid >> 5, lane = tid & 31;
    int p = blockIdx.x, P = gridDim.x;

    if (tid == 0) {
#pragma unroll
        for (int st = 0; st < NST; st++) {
            mbar_init(sb + st * 8, 1);            // full[st]
            mbar_init(sb + 64 + st * 8, 8);       // empty[st]
        }
    }
    __syncthreads();

    int ntiles = (NTILES - p + P - 1) / P;
    int GI = ntiles * KT;

    // fill global iteration f's stage
    auto fill = [&](int f) {
        int st = f & (NST - 1);
        if (f >= NST) mbar_wait(sb + 64 + st * 8, ((f >> 2) - 1) & 1);
        int tile = p + (f >> 6) * P;
        int ktf = f & 63;
        int mbf = tile & 31, nbf = tile >> 5;
        uint32_t fb = sb + st * 8;
        mbar_expect_tx(fb, STAGE_BYTES);
        uint32_t sdst = sb + SMEM_OFF + st * STAGE_BYTES;
        bulk_g2s(sdst, (const char*)g_Apack + (size_t)(mbf * 64 + ktf) * A_TILE,
                 A_TILE, fb);
        bulk_g2s(sdst + A_TILE,
                 (const char*)g_Bpack + (size_t)(nbf * 64 + ktf) * B_TILE,
                 B_TILE, fb);
    };
    if (tid == 0) {
        for (int f = 0; f < NST && f < GI; f++) fill(f);
    }

    // per-thread ldmatrix geometry (warp tile 64x48, 128B smem rows)
    int g = lane >> 3, tr = lane & 7;
    int m_warp = (wid & 1) * 64;
    int n_warp = (wid >> 1) * 48;
    int aRow0 = m_warp + (g & 1) * 8 + tr;
    int aH = g >> 1;
    int bRow0 = n_warp + (g >> 1) * 8 + tr;
    int bH = g & 1;

    for (int tile_i = 0; tile_i < ntiles; tile_i++) {
        int tile = p + tile_i * P;
        int mb = tile & 31, nb = tile >> 5;

        float acc[4][6][4];
#pragma unroll
        for (int i = 0; i < 4; i++)
#pragma unroll
            for (int j = 0; j < 6; j++)
#pragma unroll
                for (int k = 0; k < 4; k++) acc[i][j][k] = 0.f;

        for (int kt = 0; kt < KT; kt++) {
            int gi = tile_i * KT + kt;
            int st = gi & (NST - 1);
            mbar_wait(sb + st * 8, (gi >> 2) & 1);
            uint32_t As = sb + SMEM_OFF + st * STAGE_BYTES;
            uint32_t Bs = As + A_TILE;

#pragma unroll
            for (int ks = 0; ks < 4; ks++) {
                int kc = 2 * ks;
                uint32_t a0[4][4];
#pragma unroll
                for (int mt = 0; mt < 4; mt++) {
                    int r = aRow0 + mt * 16;
                    int c = (kc + aH) ^ (r & 7);
                    ldsm4(a0[mt], As + r * 128 + c * 16);
                }
                // interleave: one B ldsm, then its 8 MMAs
#pragma unroll
                for (int nt2 = 0; nt2 < 3; nt2++) {
                    int r = bRow0 + nt2 * 16;
                    int c = (kc + bH) ^ (r & 7);
                    uint32_t q[4];
                    ldsm4(q, Bs + r * 128 + c * 16);
                    if (ks == 3 && nt2 == 2 && lane == 0)
                        mbar_arrive(sb + 64 + st * 8);   // all reads issued
#pragma unroll
                    for (int mt = 0; mt < 4; mt++) {
                        mma16816(acc[mt][nt2 * 2], a0[mt], q);
                        mma16816(acc[mt][nt2 * 2 + 1], a0[mt], q + 2);
                    }
                }
            }

            // distributed refill: rotating warp issues next stage's loads
            if ((gi & 7) == wid && lane == 0) {
                int f = gi + NST;
                if (f < GI) fill(f);
            }
        }

        // epilogue: registers -> gmem (+bias); stage smem untouched
        int m0 = mb * BM + m_warp;
        int n0 = nb * BN + n_warp;
        float2 bv[6];
#pragma unroll
        for (int nt = 0; nt < 6; nt++)
            bv[nt] = *reinterpret_cast<const float2*>(
                &bias[n0 + nt * 8 + (lane & 3) * 2]);
#pragma unroll
        for (int mt = 0; mt < 4; mt++) {
#pragma unroll
            for (int nt = 0; nt < 6; nt++) {
                int row = m0 + mt * 16 + (lane >> 2);
                int col = n0 + nt * 8 + (lane & 3) * 2;
                float2 v0 = make_float2(acc[mt][nt][0] + bv[nt].x,
                                        acc[mt][nt][1] + bv[nt].y);
                float2 v1 = make_float2(acc[mt][nt][2] + bv[nt].x,
                                        acc[mt][nt][3] + bv[nt].y);
                *reinterpret_cast<float2*>(&C[(size_t)row * N_DIM + col]) = v0;
                *reinterpret_cast<float2*>(&C[(size_t)(row + 8) * N_DIM + col]) = v1;
            }
        }
    }
}

// ---------------------------------------------------------------------------
// Launch
// ---------------------------------------------------------------------------
extern "C" void kernel_launch(void* const* d_in, const int* in_sizes, int n_in,
                              void* d_out, int out_size) {
    const float* A    = (const float*)d_in[0];
    const int*   B    = (const int*)  d_in[1];
    const float* s    = (const float*)d_in[2];
    const float* bias = (const float*)d_in[3];
    float* C = (float*)d_out;

    cudaFuncSetAttribute(gemm_hmma_kernel,
                         cudaFuncAttributeMaxDynamicSharedMemorySize, SMEM_BYTES);

    int nsm = 148;
    cudaDeviceGetAttribute(&nsm, cudaDevAttrMultiProcessorCount, 0);

    convA_kernel<<<(M_DIM * 512) / 256, 256>>>(A);
    dim3 dq_grid(N_DIM / BN, K_DIM / BK);   // 64 x 64 tiles
    dequant_kernel<<<dq_grid, 192>>>(B, s);
    gemm_hmma_kernel<<<nsm, 256, SMEM_BYTES>>>(bias, C);
}